// round 11
// baseline (speedup 1.0000x reference)
#include <cuda_runtime.h>
#include <cuda_fp16.h>
#include <cstdint>

#define Bn 8
#define Cn 256
#define Hn 128
#define Wn 128
#define NE (Bn*Cn*Hn*Wn)

// act block (b,y,g): 130 rows of 64B (fp16 x32ci), packed 2 rows per 128B line:
//   byte = L*128 + c*32 + par*16   (row = 2L+par, k-chunk c=0..3)
#define ABLK   8320                  // 65 lines * 128
#define ACT_TOT ((size_t)Bn*Hn*8*ABLK)
#define WSTG   24576                 // [kx3][nt16][lane32][uint4: ks0j0,ks0j1,ks1j0,ks1j1]
#define WCONV  (48ull*WSTG)
#define ASTG   (2*ABLK)              // 16640
#define STG    (ASTG + WSTG)         // 41216
#define NSTAGE 3
#define DSMEM  (NSTAGE*STG)          // 123648
#define DSMEM_REQ (DSMEM + 1024)
#define NT 512

__device__ __align__(1024) unsigned char g_actA[ACT_TOT];
__device__ __align__(1024) unsigned char g_actB[ACT_TOT];
__device__ __align__(1024) unsigned char g_wpk[3*WCONV];
__device__ __align__(1024) unsigned char g_zero[ABLK];
__device__ float g_xm[NE];

// ---------------- helpers ----------------
static __device__ __forceinline__ uint32_t smem_u32(const void* p) {
    uint32_t r;
    asm("{ .reg .u64 t; cvta.to.shared.u64 t, %1; cvt.u32.u64 %0, t; }" : "=r"(r) : "l"(p));
    return r;
}
static __device__ __forceinline__ void cp16(uint32_t dst, const void* src) {
    asm volatile("cp.async.cg.shared.global [%0], [%1], 16;" :: "r"(dst), "l"(src) : "memory");
}
#define CP_COMMIT() asm volatile("cp.async.commit_group;" ::: "memory")
#define CP_WAIT2()  asm volatile("cp.async.wait_group 2;" ::: "memory")
#define CP_WAIT0()  asm volatile("cp.async.wait_group 0;" ::: "memory")

static __device__ __forceinline__ void ldm4(uint32_t a[4], uint32_t addr) {
    asm volatile("ldmatrix.sync.aligned.m8n8.x4.shared.b16 {%0,%1,%2,%3}, [%4];"
                 : "=r"(a[0]), "=r"(a[1]), "=r"(a[2]), "=r"(a[3]) : "r"(addr));
}
static __device__ __forceinline__ void mma16816(float d[4], const uint32_t a[4],
                                                uint32_t b0, uint32_t b1) {
    asm volatile("mma.sync.aligned.m16n8k16.row.col.f32.f16.f16.f32 "
                 "{%0,%1,%2,%3}, {%4,%5,%6,%7}, {%8,%9}, {%0,%1,%2,%3};"
                 : "+f"(d[0]), "+f"(d[1]), "+f"(d[2]), "+f"(d[3])
                 : "r"(a[0]), "r"(a[1]), "r"(a[2]), "r"(a[3]), "r"(b0), "r"(b1));
}
// store one 64B act row (row = 2L+par) into a block base (gmem, unswizzled)
static __device__ __forceinline__ void store_row64(unsigned char* blockbase, int row,
                                                   const uint32_t hv[16]) {
    unsigned char* base = blockbase + (row >> 1) * 128 + (row & 1) * 16;
#pragma unroll
    for (int c = 0; c < 4; c++)
        *(uint4*)(base + c * 32) = make_uint4(hv[4*c], hv[4*c+1], hv[4*c+2], hv[4*c+3]);
}

// ---------------- init: zero template block + act halo rows ----------------
__global__ void k_zero() {
    int i = blockIdx.x * blockDim.x + threadIdx.x;
    const uint4 z = make_uint4(0, 0, 0, 0);
    if (i < 520) { ((uint4*)g_zero)[i] = z; return; }
    int h = i - 520;
    if (h >= 2 * 8192 * 8) return;
    int j = h & 7;  h >>= 3;
    int blk = h & 8191;
    unsigned char* buf = (h >> 13) ? g_actB : g_actA;
    unsigned char* bb = buf + (size_t)blk * ABLK;
    if (j < 4) *(uint4*)(bb + j * 32) = z;                       // row 0
    else       *(uint4*)(bb + 64 * 128 + (j - 4) * 32 + 16) = z; // row 129
}

// ---------------- weight pack: uint4-fragment order, single fp16 ----------------
// u32 idx = stage*6144 + ((kx*16 + nt)*32 + lane)*4 + ks*2 + j ; stage = (ocH*3+ky)*8+g
__global__ void k_packw(const float* __restrict__ w, unsigned char* __restrict__ dstB) {
    int u = blockIdx.x * blockDim.x + threadIdx.x;
    if (u >= 294912) return;
    int within = u % 6144, stage = u / 6144;
    int g = stage & 7, kyH = stage >> 3;
    int ky = kyH % 3, ocH = kyH / 3;
    int kj = within & 3;  int ks = kj >> 1, j = kj & 1;
    int lane = (within >> 2) & 31;
    int nt   = (within >> 7) & 15;
    int kx   = within >> 11;
    int oc = ocH * 128 + nt * 8 + (lane >> 2);
    int k  = ks * 16 + (lane & 3) * 2 + j * 8;     // 0..31
    int ci0 = g * 32 + k;
    float e0 = w[((oc * Cn + ci0) * 3 + ky) * 3 + kx];
    float e1 = w[((oc * Cn + ci0 + 1) * 3 + ky) * 3 + kx];
    unsigned short h0 = __half_as_ushort(__float2half_rn(e0));
    unsigned short h1 = __half_as_ushort(__float2half_rn(e1));
    ((uint32_t*)dstB)[u] = (uint32_t)h0 | ((uint32_t)h1 << 16);
}

// ---------------- prep: act0 = fp16(mask(prelu(x)));  xm = x ----------------
__global__ void k_prep(const float* __restrict__ x, const float* __restrict__ pa,
                       float* __restrict__ xm) {
    extern __shared__ float sX[];
    const int y = blockIdx.x, b = blockIdx.y, tid = threadIdx.x;
    const float pav = pa[0];
    const float4* src = (const float4*)(x + ((size_t)b * Cn * Hn + y) * Wn);
    float4* xmd = (float4*)(xm + ((size_t)b * Cn * Hn + y) * Wn);
    for (int i = tid; i < 8192; i += 256) {
        int ci = i >> 5, p4 = i & 31;
        float4 v = src[(size_t)ci * (Hn * Wn / 4) + p4];
        ((float4*)sX)[ci * 32 + p4] = v;
        xmd[(size_t)ci * (Hn * Wn / 4) + p4] = v;    // xm init fused (replaces memcpy)
    }
    __syncthreads();
#pragma unroll 1
    for (int k = 0; k < 4; k++) {
        int t = tid + k * 256;
        int px = t & 127, g = t >> 7;
        uint32_t hv[16];
        unsigned short hprev = 0;
#pragma unroll
        for (int j = 0; j < 32; j++) {
            float v = sX[(g * 32 + j) * 128 + px];
            float tt = v >= 0.f ? v : pav * v;
            float a = fabsf(tt) >= 0.1f ? tt : 0.f;
            unsigned short hb = __half_as_ushort(__float2half_rn(a));
            if (j & 1) hv[j >> 1] = (uint32_t)hprev | ((uint32_t)hb << 16);
            else hprev = hb;
        }
        store_row64(g_actA + ((size_t)(b * Hn + y) * 8 + g) * ABLK, px + 1, hv);
    }
}

// ---------------- main conv: mma.sync implicit GEMM, 3-stage pipeline ----------------
// 512 thr: 8 M-warps (32 px) x 2 N-warps (64 oc); M=256 (2 rows), N=128
template <int MODE>
__global__ __launch_bounds__(NT, 1)
void conv_mma(const unsigned char* __restrict__ actIn,
              const unsigned char* __restrict__ wcv,
              const float* __restrict__ bias,
              float* __restrict__ xm,
              const float* __restrict__ pa,
              unsigned char* __restrict__ actOut,
              float* __restrict__ out) {
    extern __shared__ __align__(16) unsigned char dsm_raw[];
    const uint32_t sb0 = smem_u32(dsm_raw);
    const uint32_t sb = (sb0 + 1023u) & ~1023u;
    unsigned char* dsm = dsm_raw + (sb - sb0);
    const int tid = threadIdx.x, lane = tid & 31, wid = tid >> 5;
    const int ocH = blockIdx.x, y = blockIdx.y * 2, b = blockIdx.z;
    const int mw = wid & 7;
    const int ablk = mw >> 2;
    const int pxb = (mw & 3) * 32;
    const int ntB = (wid >> 3) * 8;

    float d[2][8][4];
#pragma unroll
    for (int mt = 0; mt < 2; mt++)
#pragma unroll
        for (int nt = 0; nt < 8; nt++)
#pragma unroll
            for (int q = 0; q < 4; q++) d[mt][nt][q] = 0.f;

    #define ISSUE(IT) do { \
        int s_ = (IT) % NSTAGE; \
        int ky_ = (IT) >> 3, g_ = (IT) & 7; \
        int ys0_ = y + ky_ - 1; \
        const unsigned char* a0 = ((unsigned)ys0_ < (unsigned)Hn) \
            ? actIn + ((size_t)(b * Hn + ys0_) * 8 + g_) * ABLK : g_zero; \
        const unsigned char* a1 = ((unsigned)(ys0_ + 1) < (unsigned)Hn) \
            ? actIn + ((size_t)(b * Hn + ys0_ + 1) * 8 + g_) * ABLK : g_zero; \
        const unsigned char* wSrc = wcv + (size_t)((ocH * 3 + ky_) * 8 + g_) * WSTG; \
        uint32_t ab = sb + s_ * STG; \
        for (int i = tid; i < 1040; i += NT) { \
            int bk = i >= 520; int ii = i - bk * 520; \
            int L = ii >> 3, cc = (ii >> 1) & 3, par = ii & 1; \
            cp16(ab + bk * ABLK + L * 128 + ((cc ^ (L & 3)) << 5) + (par << 4), \
                 (bk ? a1 : a0) + L * 128 + cc * 32 + par * 16); \
        } \
        uint32_t wb = ab + ASTG; \
        for (int i = tid; i < 1536; i += NT) \
            cp16(wb + i * 16, wSrc + (size_t)i * 16); \
        CP_COMMIT(); \
    } while (0)

    ISSUE(0); ISSUE(1); ISSUE(2);

    int s = 0;
    for (int it = 0; it < 24; it++) {
        CP_WAIT2();
        __syncthreads();
        if (it >= 1 && it + 2 < 24) ISSUE(it + 2);   // overwrites stage (it-1)%3: readers done
        const uint32_t aB = sb + s * STG + ablk * ABLK;
        const unsigned char* wS = dsm + s * STG + ASTG;
#pragma unroll
        for (int kx = 0; kx < 3; kx++) {
            uint32_t aF[2][2][4];                     // [ks][mt]
#pragma unroll
            for (int mt = 0; mt < 2; mt++) {
                int row = pxb + mt * 16 + (lane & 15) + kx;   // 0..129
                int L = row >> 1, par = row & 1;
                uint32_t base = aB + L * 128 + (par << 4);
#pragma unroll
                for (int ks = 0; ks < 2; ks++) {
                    int c = ks * 2 + (lane >> 4);
                    ldm4(aF[ks][mt], base + ((c ^ (L & 3)) << 5));
                }
            }
            const uint4* wrow = (const uint4*)(wS + ((size_t)(kx * 16 + ntB)) * 512);
#pragma unroll
            for (int nt = 0; nt < 8; nt++) {
                uint4 wq = wrow[nt * 32 + lane];      // LDS.128: both ks fragments
                mma16816(d[0][nt], aF[0][0], wq.x, wq.y);
                mma16816(d[1][nt], aF[0][1], wq.x, wq.y);
                mma16816(d[0][nt], aF[1][0], wq.z, wq.w);
                mma16816(d[1][nt], aF[1][1], wq.z, wq.w);
            }
        }
        if (++s == NSTAGE) s = 0;
    }
    #undef ISSUE
    CP_WAIT0();

    // ---- epilogue: 2 passes of 128 M-rows through a smem fp32 tile ----
    float* sD = (float*)dsm;                       // 128 x 129 fp32 = 66048 B
    const float pav = pa[0];
#pragma unroll 1
    for (int p = 0; p < 2; p++) {
        __syncthreads();
        if ((mw >> 2) == p) {
#pragma unroll
            for (int mt = 0; mt < 2; mt++) {
                int m0 = (mw & 3) * 32 + mt * 16 + (lane >> 2);
                int n0base = ntB * 8 + (lane & 3) * 2;
#pragma unroll
                for (int nt = 0; nt < 8; nt++) {
                    int n0 = n0base + nt * 8;
                    sD[m0 * 129 + n0]           = d[mt][nt][0];
                    sD[m0 * 129 + n0 + 1]       = d[mt][nt][1];
                    sD[(m0 + 8) * 129 + n0]     = d[mt][nt][2];
                    sD[(m0 + 8) * 129 + n0 + 1] = d[mt][nt][3];
                }
            }
        }
        __syncthreads();
        const int px = tid & 127, gl = (tid >> 7) & 3;
        const int yout = y + p;
        const int oc0 = ocH * 128 + gl * 32;
        if (MODE == 1) {
            uint32_t hv[16];
            unsigned short hprev = 0;
#pragma unroll
            for (int j = 0; j < 32; j++) {
                float v = sD[px * 129 + gl * 32 + j] + bias[oc0 + j];
                size_t xi = ((size_t)(b * Cn + oc0 + j) * Hn + yout) * Wn + px;
                float m = fmaxf(xm[xi], v);
                xm[xi] = m;
                float tt = m >= 0.f ? m : pav * m;
                float a = fabsf(tt) >= 0.1f ? tt : 0.f;
                unsigned short hb = __half_as_ushort(__float2half_rn(a));
                if (j & 1) hv[j >> 1] = (uint32_t)hprev | ((uint32_t)hb << 16);
                else hprev = hb;
            }
            int gOut = ocH * 4 + gl;
            store_row64(actOut + ((size_t)(b * Hn + yout) * 8 + gOut) * ABLK, px + 1, hv);
        } else {
#pragma unroll
            for (int j = 0; j < 32; j++) {
                float v = sD[px * 129 + gl * 32 + j] + bias[oc0 + j];
                out[((size_t)(b * Cn + oc0 + j) * Hn + yout) * Wn + px] = v;
            }
        }
    }
}

// ---------------- host ----------------
extern "C" void kernel_launch(void* const* d_in, const int* in_sizes, int n_in,
                              void* d_out, int out_size) {
    const float* x  = (const float*)d_in[0];
    const float* w1 = (const float*)d_in[1];
    const float* b1 = (const float*)d_in[2];
    const float* w2 = (const float*)d_in[3];
    const float* b2 = (const float*)d_in[4];
    const float* w3 = (const float*)d_in[5];
    const float* b3 = (const float*)d_in[6];
    const float* pa = (const float*)d_in[7];
    float* out = (float*)d_out;

    unsigned char *wpk, *actA, *actB;
    float* xm;
    cudaGetSymbolAddress((void**)&wpk,  g_wpk);
    cudaGetSymbolAddress((void**)&xm,   g_xm);
    cudaGetSymbolAddress((void**)&actA, g_actA);
    cudaGetSymbolAddress((void**)&actB, g_actB);

    cudaFuncSetAttribute(conv_mma<1>, cudaFuncAttributeMaxDynamicSharedMemorySize, DSMEM_REQ);
    cudaFuncSetAttribute(conv_mma<3>, cudaFuncAttributeMaxDynamicSharedMemorySize, DSMEM_REQ);
    cudaFuncSetAttribute(k_prep, cudaFuncAttributeMaxDynamicSharedMemorySize, 131072);

    k_zero<<<(520 + 131072 + 255) / 256, 256>>>();
    k_packw<<<1152, 256>>>(w1, wpk);
    k_packw<<<1152, 256>>>(w2, wpk + WCONV);
    k_packw<<<1152, 256>>>(w3, wpk + 2 * WCONV);
    k_prep<<<dim3(Hn, Bn), 256, 131072>>>(x, pa, xm);

    dim3 grid(2, Hn / 2, Bn);
    conv_mma<1><<<grid, NT, DSMEM_REQ>>>(actA, wpk,             b1, xm, pa, actB, nullptr);
    conv_mma<1><<<grid, NT, DSMEM_REQ>>>(actB, wpk + WCONV,     b2, xm, pa, actA, nullptr);
    conv_mma<3><<<grid, NT, DSMEM_REQ>>>(actA, wpk + 2 * WCONV, b3, xm, pa, nullptr, out);
}

// round 12
// speedup vs baseline: 1.0930x; 1.0930x over previous
#include <cuda_runtime.h>
#include <cuda_fp16.h>
#include <cstdint>

#define Bn 8
#define Cn 256
#define Hn 128
#define Wn 128
#define NE (Bn*Cn*Hn*Wn)

// act block (b,y,g): 130 rows of 64B (fp16 x32ci), packed 2 rows per 128B line:
//   byte = L*128 + c*32 + par*16   (row = 2L+par, k-chunk c=0..3)
#define ABLK   8320                  // 65 lines * 128
#define ACT_TOT ((size_t)Bn*Hn*8*ABLK)
#define WSTG   24576                 // [kx3][nt16][lane32][uint4: ks0j0,ks0j1,ks1j0,ks1j1]
#define WCONV  (48ull*WSTG)
#define STG    (ABLK + WSTG)         // 32896
#define NSTAGE 3
#define DSMEM  (NSTAGE*STG)          // 98688  (>= 66048 epilogue tile)
#define DSMEM_REQ DSMEM
#define NT 256                       // threads per conv CTA; 2 CTAs/SM

__device__ __align__(1024) unsigned char g_actA[ACT_TOT];
__device__ __align__(1024) unsigned char g_actB[ACT_TOT];
__device__ __align__(1024) unsigned char g_wpk[3*WCONV];
__device__ __align__(1024) unsigned char g_zero[ABLK];
__device__ float g_xm[NE];

// ---------------- helpers ----------------
static __device__ __forceinline__ uint32_t smem_u32(const void* p) {
    uint32_t r;
    asm("{ .reg .u64 t; cvta.to.shared.u64 t, %1; cvt.u32.u64 %0, t; }" : "=r"(r) : "l"(p));
    return r;
}
static __device__ __forceinline__ void cp16(uint32_t dst, const void* src) {
    asm volatile("cp.async.cg.shared.global [%0], [%1], 16;" :: "r"(dst), "l"(src) : "memory");
}
#define CP_COMMIT() asm volatile("cp.async.commit_group;" ::: "memory")
#define CP_WAIT2()  asm volatile("cp.async.wait_group 2;" ::: "memory")
#define CP_WAIT0()  asm volatile("cp.async.wait_group 0;" ::: "memory")

static __device__ __forceinline__ void ldm4(uint32_t a[4], uint32_t addr) {
    asm volatile("ldmatrix.sync.aligned.m8n8.x4.shared.b16 {%0,%1,%2,%3}, [%4];"
                 : "=r"(a[0]), "=r"(a[1]), "=r"(a[2]), "=r"(a[3]) : "r"(addr));
}
static __device__ __forceinline__ void mma16816(float d[4], const uint32_t a[4],
                                                uint32_t b0, uint32_t b1) {
    asm volatile("mma.sync.aligned.m16n8k16.row.col.f32.f16.f16.f32 "
                 "{%0,%1,%2,%3}, {%4,%5,%6,%7}, {%8,%9}, {%0,%1,%2,%3};"
                 : "+f"(d[0]), "+f"(d[1]), "+f"(d[2]), "+f"(d[3])
                 : "r"(a[0]), "r"(a[1]), "r"(a[2]), "r"(a[3]), "r"(b0), "r"(b1));
}
// store one 64B act row (row = 2L+par) into a block base (gmem, unswizzled)
static __device__ __forceinline__ void store_row64(unsigned char* blockbase, int row,
                                                   const uint32_t hv[16]) {
    unsigned char* base = blockbase + (row >> 1) * 128 + (row & 1) * 16;
#pragma unroll
    for (int c = 0; c < 4; c++)
        *(uint4*)(base + c * 32) = make_uint4(hv[4*c], hv[4*c+1], hv[4*c+2], hv[4*c+3]);
}

// ---------------- init: zero template block + act halo rows ----------------
__global__ void k_zero() {
    int i = blockIdx.x * blockDim.x + threadIdx.x;
    const uint4 z = make_uint4(0, 0, 0, 0);
    if (i < 520) { ((uint4*)g_zero)[i] = z; return; }
    int h = i - 520;
    if (h >= 2 * 8192 * 8) return;
    int j = h & 7;  h >>= 3;
    int blk = h & 8191;
    unsigned char* buf = (h >> 13) ? g_actB : g_actA;
    unsigned char* bb = buf + (size_t)blk * ABLK;
    if (j < 4) *(uint4*)(bb + j * 32) = z;                       // row 0
    else       *(uint4*)(bb + 64 * 128 + (j - 4) * 32 + 16) = z; // row 129
}

// ---------------- weight pack: uint4-fragment order, single fp16 ----------------
// u32 idx = stage*6144 + ((kx*16 + nt)*32 + lane)*4 + ks*2 + j ; stage = (ocH*3+ky)*8+g
__global__ void k_packw(const float* __restrict__ w, unsigned char* __restrict__ dstB) {
    int u = blockIdx.x * blockDim.x + threadIdx.x;
    if (u >= 294912) return;
    int within = u % 6144, stage = u / 6144;
    int g = stage & 7, kyH = stage >> 3;
    int ky = kyH % 3, ocH = kyH / 3;
    int kj = within & 3;  int ks = kj >> 1, j = kj & 1;
    int lane = (within >> 2) & 31;
    int nt   = (within >> 7) & 15;
    int kx   = within >> 11;
    int oc = ocH * 128 + nt * 8 + (lane >> 2);
    int k  = ks * 16 + (lane & 3) * 2 + j * 8;     // 0..31
    int ci0 = g * 32 + k;
    float e0 = w[((oc * Cn + ci0) * 3 + ky) * 3 + kx];
    float e1 = w[((oc * Cn + ci0 + 1) * 3 + ky) * 3 + kx];
    unsigned short h0 = __half_as_ushort(__float2half_rn(e0));
    unsigned short h1 = __half_as_ushort(__float2half_rn(e1));
    ((uint32_t*)dstB)[u] = (uint32_t)h0 | ((uint32_t)h1 << 16);
}

// ---------------- prep: act0 = fp16(mask(prelu(x)));  xm = x ----------------
__global__ void k_prep(const float* __restrict__ x, const float* __restrict__ pa,
                       float* __restrict__ xm) {
    extern __shared__ float sX[];
    const int y = blockIdx.x, b = blockIdx.y, tid = threadIdx.x;
    const float pav = pa[0];
    const float4* src = (const float4*)(x + ((size_t)b * Cn * Hn + y) * Wn);
    float4* xmd = (float4*)(xm + ((size_t)b * Cn * Hn + y) * Wn);
    for (int i = tid; i < 8192; i += 256) {
        int ci = i >> 5, p4 = i & 31;
        float4 v = src[(size_t)ci * (Hn * Wn / 4) + p4];
        ((float4*)sX)[ci * 32 + p4] = v;
        xmd[(size_t)ci * (Hn * Wn / 4) + p4] = v;
    }
    __syncthreads();
#pragma unroll 1
    for (int k = 0; k < 4; k++) {
        int t = tid + k * 256;
        int px = t & 127, g = t >> 7;
        uint32_t hv[16];
        unsigned short hprev = 0;
#pragma unroll
        for (int j = 0; j < 32; j++) {
            float v = sX[(g * 32 + j) * 128 + px];
            float tt = v >= 0.f ? v : pav * v;
            float a = fabsf(tt) >= 0.1f ? tt : 0.f;
            unsigned short hb = __half_as_ushort(__float2half_rn(a));
            if (j & 1) hv[j >> 1] = (uint32_t)hprev | ((uint32_t)hb << 16);
            else hprev = hb;
        }
        store_row64(g_actA + ((size_t)(b * Hn + y) * 8 + g) * ABLK, px + 1, hv);
    }
}

// ---------------- main conv: mma.sync implicit GEMM, M=128, 2 CTAs/SM ----------------
// 256 thr: 4 M-warps (32 px) x 2 N-warps (64 oc)
template <int MODE>
__global__ __launch_bounds__(NT, 2)
void conv_mma(const unsigned char* __restrict__ actIn,
              const unsigned char* __restrict__ wcv,
              const float* __restrict__ bias,
              float* __restrict__ xm,
              const float* __restrict__ pa,
              unsigned char* __restrict__ actOut,
              float* __restrict__ out) {
    extern __shared__ __align__(16) unsigned char dsm[];
    const uint32_t sb = smem_u32(dsm);
    const int tid = threadIdx.x, lane = tid & 31, wid = tid >> 5;
    const int ocH = blockIdx.x, y = blockIdx.y, b = blockIdx.z;
    const int mw = wid & 3;                  // M-warp 0..3 (32 px each)
    const int pxb = mw * 32;
    const int ntB = (wid >> 2) * 8;          // N half

    float d[2][8][4];
#pragma unroll
    for (int mt = 0; mt < 2; mt++)
#pragma unroll
        for (int nt = 0; nt < 8; nt++)
#pragma unroll
            for (int q = 0; q < 4; q++) d[mt][nt][q] = 0.f;

    #define ISSUE(IT) do { \
        int s_ = (IT) % NSTAGE; \
        int ky_ = (IT) >> 3, g_ = (IT) & 7; \
        int ys_ = y + ky_ - 1; \
        const unsigned char* aSrc = ((unsigned)ys_ < (unsigned)Hn) \
            ? actIn + ((size_t)(b * Hn + ys_) * 8 + g_) * ABLK : g_zero; \
        const unsigned char* wSrc = wcv + (size_t)((ocH * 3 + ky_) * 8 + g_) * WSTG; \
        uint32_t ab = sb + s_ * STG; \
        for (int i = tid; i < 520; i += NT) { \
            int L = i >> 3, cc = (i >> 1) & 3, par = i & 1; \
            cp16(ab + L * 128 + ((cc ^ (L & 3)) << 5) + (par << 4), \
                 aSrc + L * 128 + cc * 32 + par * 16); \
        } \
        uint32_t wb = ab + ABLK; \
        for (int i = tid; i < 1536; i += NT) \
            cp16(wb + i * 16, wSrc + (size_t)i * 16); \
        CP_COMMIT(); \
    } while (0)

    ISSUE(0); ISSUE(1); ISSUE(2);

    int s = 0;
    for (int it = 0; it < 24; it++) {
        CP_WAIT2();
        __syncthreads();
        if (it >= 1 && it + 2 < 24) ISSUE(it + 2);   // overwrites stage (it-1)%3: readers done
        const uint32_t aB = sb + s * STG;
        const unsigned char* wS = dsm + s * STG + ABLK;
#pragma unroll
        for (int kx = 0; kx < 3; kx++) {
            uint32_t aF[2][2][4];                     // [ks][mt]
#pragma unroll
            for (int mt = 0; mt < 2; mt++) {
                int row = pxb + mt * 16 + (lane & 15) + kx;   // 0..129
                int L = row >> 1, par = row & 1;
                uint32_t base = aB + L * 128 + (par << 4);
#pragma unroll
                for (int ks = 0; ks < 2; ks++) {
                    int c = ks * 2 + (lane >> 4);
                    ldm4(aF[ks][mt], base + ((c ^ (L & 3)) << 5));
                }
            }
            const uint4* wrow = (const uint4*)(wS + ((size_t)(kx * 16 + ntB)) * 512);
#pragma unroll
            for (int nt = 0; nt < 8; nt++) {
                uint4 wq = wrow[nt * 32 + lane];      // LDS.128: both ks fragments
                mma16816(d[0][nt], aF[0][0], wq.x, wq.y);
                mma16816(d[1][nt], aF[0][1], wq.x, wq.y);
                mma16816(d[0][nt], aF[1][0], wq.z, wq.w);
                mma16816(d[1][nt], aF[1][1], wq.z, wq.w);
            }
        }
        if (++s == NSTAGE) s = 0;
    }
    #undef ISSUE
    CP_WAIT0();
    __syncthreads();

    // ---- epilogue: fragments -> smem fp32 tile [128][129] ----
    float* sD = (float*)dsm;                       // 66048 B <= DSMEM
#pragma unroll
    for (int mt = 0; mt < 2; mt++) {
        int m0 = pxb + mt * 16 + (lane >> 2);
        int n0base = ntB * 8 + (lane & 3) * 2;
#pragma unroll
        for (int nt = 0; nt < 8; nt++) {
            int n0 = n0base + nt * 8;
            sD[m0 * 129 + n0]           = d[mt][nt][0];
            sD[m0 * 129 + n0 + 1]       = d[mt][nt][1];
            sD[(m0 + 8) * 129 + n0]     = d[mt][nt][2];
            sD[(m0 + 8) * 129 + n0 + 1] = d[mt][nt][3];
        }
    }
    __syncthreads();

    const float pav = pa[0];
#pragma unroll 1
    for (int k = 0; k < 2; k++) {
        int t = tid + k * NT;
        int px = t & 127, gl = t >> 7;               // gl 0..3
        int oc0 = ocH * 128 + gl * 32;
        if (MODE == 1) {
            uint32_t hv[16];
            unsigned short hprev = 0;
#pragma unroll
            for (int j = 0; j < 32; j++) {
                float v = sD[px * 129 + gl * 32 + j] + bias[oc0 + j];
                size_t xi = ((size_t)(b * Cn + oc0 + j) * Hn + y) * Wn + px;
                float m = fmaxf(xm[xi], v);
                xm[xi] = m;
                float tt = m >= 0.f ? m : pav * m;
                float a = fabsf(tt) >= 0.1f ? tt : 0.f;
                unsigned short hb = __half_as_ushort(__float2half_rn(a));
                if (j & 1) hv[j >> 1] = (uint32_t)hprev | ((uint32_t)hb << 16);
                else hprev = hb;
            }
            int gOut = ocH * 4 + gl;
            store_row64(actOut + ((size_t)(b * Hn + y) * 8 + gOut) * ABLK, px + 1, hv);
        } else {
#pragma unroll
            for (int j = 0; j < 32; j++) {
                float v = sD[px * 129 + gl * 32 + j] + bias[oc0 + j];
                out[((size_t)(b * Cn + oc0 + j) * Hn + y) * Wn + px] = v;
            }
        }
    }
}

// ---------------- host ----------------
extern "C" void kernel_launch(void* const* d_in, const int* in_sizes, int n_in,
                              void* d_out, int out_size) {
    const float* x  = (const float*)d_in[0];
    const float* w1 = (const float*)d_in[1];
    const float* b1 = (const float*)d_in[2];
    const float* w2 = (const float*)d_in[3];
    const float* b2 = (const float*)d_in[4];
    const float* w3 = (const float*)d_in[5];
    const float* b3 = (const float*)d_in[6];
    const float* pa = (const float*)d_in[7];
    float* out = (float*)d_out;

    unsigned char *wpk, *actA, *actB;
    float* xm;
    cudaGetSymbolAddress((void**)&wpk,  g_wpk);
    cudaGetSymbolAddress((void**)&xm,   g_xm);
    cudaGetSymbolAddress((void**)&actA, g_actA);
    cudaGetSymbolAddress((void**)&actB, g_actB);

    cudaFuncSetAttribute(conv_mma<1>, cudaFuncAttributeMaxDynamicSharedMemorySize, DSMEM_REQ);
    cudaFuncSetAttribute(conv_mma<3>, cudaFuncAttributeMaxDynamicSharedMemorySize, DSMEM_REQ);
    cudaFuncSetAttribute(k_prep, cudaFuncAttributeMaxDynamicSharedMemorySize, 131072);

    k_zero<<<(520 + 131072 + 255) / 256, 256>>>();
    k_packw<<<1152, 256>>>(w1, wpk);
    k_packw<<<1152, 256>>>(w2, wpk + WCONV);
    k_packw<<<1152, 256>>>(w3, wpk + 2 * WCONV);
    k_prep<<<dim3(Hn, Bn), 256, 131072>>>(x, pa, xm);

    dim3 grid(2, Hn, Bn);
    conv_mma<1><<<grid, NT, DSMEM_REQ>>>(actA, wpk,             b1, xm, pa, actB, nullptr);
    conv_mma<1><<<grid, NT, DSMEM_REQ>>>(actB, wpk + WCONV,     b2, xm, pa, actA, nullptr);
    conv_mma<3><<<grid, NT, DSMEM_REQ>>>(actA, wpk + 2 * WCONV, b3, xm, pa, nullptr, out);
}

// round 13
// speedup vs baseline: 1.0995x; 1.0060x over previous
#include <cuda_runtime.h>
#include <cuda_fp16.h>
#include <cstdint>

#define Bn 8
#define Cn 256
#define Hn 128
#define Wn 128
#define NE (Bn*Cn*Hn*Wn)

// act block (b,y,g): 130 rows of 64B (fp16 x32ci), packed 2 rows per 128B line:
//   byte = L*128 + c*32 + par*16   (row = 2L+par, k-chunk c=0..3)
#define ABLK   8320                  // 65 lines * 128
#define ACT_TOT ((size_t)Bn*Hn*8*ABLK)
#define WSTG   24576                 // [kx3][nt16][lane32][uint4: ks0j0,ks0j1,ks1j0,ks1j1]
#define WCONV  (48ull*WSTG)
#define STG    (ABLK + WSTG)         // 32896
#define NSTAGE 3
#define DSMEM  (NSTAGE*STG)          // 98688  (>= 66048 epilogue tile)
#define NT 256                       // threads per conv CTA; 2 CTAs/SM

__device__ __align__(1024) unsigned char g_actA[ACT_TOT];
__device__ __align__(1024) unsigned char g_actB[ACT_TOT];
__device__ __align__(1024) unsigned char g_wpk[3*WCONV];
__device__ __align__(1024) unsigned char g_zero[ABLK];
__device__ float g_xm[NE];

// ---------------- helpers ----------------
static __device__ __forceinline__ uint32_t smem_u32(const void* p) {
    uint32_t r;
    asm("{ .reg .u64 t; cvta.to.shared.u64 t, %1; cvt.u32.u64 %0, t; }" : "=r"(r) : "l"(p));
    return r;
}
static __device__ __forceinline__ void cp16(uint32_t dst, const void* src) {
    asm volatile("cp.async.cg.shared.global [%0], [%1], 16;" :: "r"(dst), "l"(src) : "memory");
}
static __device__ __forceinline__ void mbar_init(uint32_t m, uint32_t cnt) {
    asm volatile("mbarrier.init.shared.b64 [%0], %1;" :: "r"(m), "r"(cnt) : "memory");
}
static __device__ __forceinline__ void cp_arrive(uint32_t m) {
    asm volatile("cp.async.mbarrier.arrive.noinc.shared::cta.b64 [%0];" :: "r"(m) : "memory");
}
static __device__ __forceinline__ void mbar_arrive(uint32_t m) {
    asm volatile("mbarrier.arrive.shared::cta.b64 _, [%0];" :: "r"(m) : "memory");
}
static __device__ __forceinline__ void mbar_wait(uint32_t m, uint32_t par) {
    uint32_t done = 0;
    while (!done) {
        asm volatile("{ .reg .pred p; mbarrier.try_wait.parity.acquire.cta.shared::cta.b64 p, [%1], %2, 0x989680; selp.b32 %0,1,0,p; }"
                     : "=r"(done) : "r"(m), "r"(par) : "memory");
    }
}
static __device__ __forceinline__ void ldm4(uint32_t a[4], uint32_t addr) {
    asm volatile("ldmatrix.sync.aligned.m8n8.x4.shared.b16 {%0,%1,%2,%3}, [%4];"
                 : "=r"(a[0]), "=r"(a[1]), "=r"(a[2]), "=r"(a[3]) : "r"(addr));
}
static __device__ __forceinline__ void mma16816(float d[4], const uint32_t a[4],
                                                uint32_t b0, uint32_t b1) {
    asm volatile("mma.sync.aligned.m16n8k16.row.col.f32.f16.f16.f32 "
                 "{%0,%1,%2,%3}, {%4,%5,%6,%7}, {%8,%9}, {%0,%1,%2,%3};"
                 : "+f"(d[0]), "+f"(d[1]), "+f"(d[2]), "+f"(d[3])
                 : "r"(a[0]), "r"(a[1]), "r"(a[2]), "r"(a[3]), "r"(b0), "r"(b1));
}
// store one 64B act row (row = 2L+par) into a block base (gmem, unswizzled)
static __device__ __forceinline__ void store_row64(unsigned char* blockbase, int row,
                                                   const uint32_t hv[16]) {
    unsigned char* base = blockbase + (row >> 1) * 128 + (row & 1) * 16;
#pragma unroll
    for (int c = 0; c < 4; c++)
        *(uint4*)(base + c * 32) = make_uint4(hv[4*c], hv[4*c+1], hv[4*c+2], hv[4*c+3]);
}

// ---------------- init: zero template block + act halo rows ----------------
__global__ void k_zero() {
    int i = blockIdx.x * blockDim.x + threadIdx.x;
    const uint4 z = make_uint4(0, 0, 0, 0);
    if (i < 520) { ((uint4*)g_zero)[i] = z; return; }
    int h = i - 520;
    if (h >= 2 * 8192 * 8) return;
    int j = h & 7;  h >>= 3;
    int blk = h & 8191;
    unsigned char* buf = (h >> 13) ? g_actB : g_actA;
    unsigned char* bb = buf + (size_t)blk * ABLK;
    if (j < 4) *(uint4*)(bb + j * 32) = z;                       // row 0
    else       *(uint4*)(bb + 64 * 128 + (j - 4) * 32 + 16) = z; // row 129
}

// ---------------- weight pack: uint4-fragment order, single fp16 ----------------
// u32 idx = stage*6144 + ((kx*16 + nt)*32 + lane)*4 + ks*2 + j ; stage = (ocH*3+ky)*8+g
__global__ void k_packw(const float* __restrict__ w, unsigned char* __restrict__ dstB) {
    int u = blockIdx.x * blockDim.x + threadIdx.x;
    if (u >= 294912) return;
    int within = u % 6144, stage = u / 6144;
    int g = stage & 7, kyH = stage >> 3;
    int ky = kyH % 3, ocH = kyH / 3;
    int kj = within & 3;  int ks = kj >> 1, j = kj & 1;
    int lane = (within >> 2) & 31;
    int nt   = (within >> 7) & 15;
    int kx   = within >> 11;
    int oc = ocH * 128 + nt * 8 + (lane >> 2);
    int k  = ks * 16 + (lane & 3) * 2 + j * 8;     // 0..31
    int ci0 = g * 32 + k;
    float e0 = w[((oc * Cn + ci0) * 3 + ky) * 3 + kx];
    float e1 = w[((oc * Cn + ci0 + 1) * 3 + ky) * 3 + kx];
    unsigned short h0 = __half_as_ushort(__float2half_rn(e0));
    unsigned short h1 = __half_as_ushort(__float2half_rn(e1));
    ((uint32_t*)dstB)[u] = (uint32_t)h0 | ((uint32_t)h1 << 16);
}

// ---------------- prep: act0 = fp16(mask(prelu(x))) ----------------
__global__ void k_prep(const float* __restrict__ x, const float* __restrict__ pa) {
    extern __shared__ float sX[];
    const int y = blockIdx.x, b = blockIdx.y, tid = threadIdx.x;
    const float pav = pa[0];
    const float4* src = (const float4*)(x + ((size_t)b * Cn * Hn + y) * Wn);
    for (int i = tid; i < 8192; i += 256) {
        int ci = i >> 5, p4 = i & 31;
        ((float4*)sX)[ci * 32 + p4] = src[(size_t)ci * (Hn * Wn / 4) + p4];
    }
    __syncthreads();
#pragma unroll 1
    for (int k = 0; k < 4; k++) {
        int t = tid + k * 256;
        int px = t & 127, g = t >> 7;
        uint32_t hv[16];
        unsigned short hprev = 0;
#pragma unroll
        for (int j = 0; j < 32; j++) {
            float v = sX[(g * 32 + j) * 128 + px];
            float tt = v >= 0.f ? v : pav * v;
            float a = fabsf(tt) >= 0.1f ? tt : 0.f;
            unsigned short hb = __half_as_ushort(__float2half_rn(a));
            if (j & 1) hv[j >> 1] = (uint32_t)hprev | ((uint32_t)hb << 16);
            else hprev = hb;
        }
        store_row64(g_actA + ((size_t)(b * Hn + y) * 8 + g) * ABLK, px + 1, hv);
    }
}

// ---------------- main conv: mma.sync implicit GEMM, mbarrier ring ----------------
// 256 thr: 4 M-warps (32 px) x 2 N-warps (64 oc); self-paced warps, 2 CTAs/SM
// MODE 1: y=conv+bias; m=max(aux,y); xm=m; actOut=pack(mask(prelu(m)))
// MODE 3: out(NCHW fp32) = conv+bias
template <int MODE>
__global__ __launch_bounds__(NT, 2)
void conv_mma(const unsigned char* __restrict__ actIn,
              const unsigned char* __restrict__ wcv,
              const float* __restrict__ bias,
              const float* __restrict__ aux,
              float* __restrict__ xmOut,
              const float* __restrict__ pa,
              unsigned char* __restrict__ actOut,
              float* __restrict__ out) {
    extern __shared__ __align__(16) unsigned char dsm[];
    __shared__ __align__(8) unsigned long long barsto[6];   // full[0..2], empty[0..2]
    const uint32_t sb = smem_u32(dsm);
    const uint32_t bbase = smem_u32(barsto);
    const int tid = threadIdx.x, lane = tid & 31, wid = tid >> 5;
    const int ocH = blockIdx.x, y = blockIdx.y, b = blockIdx.z;
    const int mw = wid & 3;                  // M-warp 0..3 (32 px each)
    const int pxb = mw * 32;
    const int ntB = (wid >> 2) * 8;          // N half

    if (tid == 0) {
        for (int s2 = 0; s2 < NSTAGE; s2++) {
            mbar_init(bbase + 8 * s2, NT);          // full: one cp-arrive per thread
            mbar_init(bbase + 24 + 8 * s2, 8);      // empty: one arrive per warp
        }
    }
    __syncthreads();

    float d[2][8][4];
#pragma unroll
    for (int mt = 0; mt < 2; mt++)
#pragma unroll
        for (int nt = 0; nt < 8; nt++)
#pragma unroll
            for (int q = 0; q < 4; q++) d[mt][nt][q] = 0.f;

    // issue this thread's cp slice for iteration IT (stage IT%3)
    #define ISSUE(IT) do { \
        int it_ = (IT); \
        int s_ = it_ % NSTAGE; \
        if (it_ >= NSTAGE) mbar_wait(bbase + 24 + 8 * s_, (it_ / NSTAGE - 1) & 1); \
        int ky_ = it_ >> 3, g_ = it_ & 7; \
        int ys_ = y + ky_ - 1; \
        const unsigned char* aSrc = ((unsigned)ys_ < (unsigned)Hn) \
            ? actIn + ((size_t)(b * Hn + ys_) * 8 + g_) * ABLK : g_zero; \
        const unsigned char* wSrc = wcv + (size_t)((ocH * 3 + ky_) * 8 + g_) * WSTG; \
        uint32_t ab = sb + s_ * STG; \
        for (int i = tid; i < 520; i += NT) { \
            int L = i >> 3, cc = (i >> 1) & 3, par = i & 1; \
            cp16(ab + L * 128 + ((cc ^ (L & 3)) << 5) + (par << 4), \
                 aSrc + L * 128 + cc * 32 + par * 16); \
        } \
        uint32_t wb = ab + ABLK; \
        for (int i = tid; i < 1536; i += NT) \
            cp16(wb + i * 16, wSrc + (size_t)i * 16); \
        cp_arrive(bbase + 8 * s_); \
    } while (0)

    ISSUE(0); ISSUE(1); ISSUE(2);

    int s = 0;
    for (int it = 0; it < 24; it++) {
        mbar_wait(bbase + 8 * s, (it / NSTAGE) & 1);     // full[s]
        const uint32_t aB = sb + s * STG;
        const unsigned char* wS = dsm + s * STG + ABLK;
#pragma unroll
        for (int kx = 0; kx < 3; kx++) {
            uint32_t aF[2][2][4];                     // [ks][mt]
#pragma unroll
            for (int mt = 0; mt < 2; mt++) {
                int row = pxb + mt * 16 + (lane & 15) + kx;   // 0..129
                int L = row >> 1, par = row & 1;
                uint32_t base = aB + L * 128 + (par << 4);
#pragma unroll
                for (int ks = 0; ks < 2; ks++) {
                    int c = ks * 2 + (lane >> 4);
                    ldm4(aF[ks][mt], base + ((c ^ (L & 3)) << 5));
                }
            }
            const uint4* wrow = (const uint4*)(wS + ((size_t)(kx * 16 + ntB)) * 512);
#pragma unroll
            for (int nt = 0; nt < 8; nt++) {
                uint4 wq = wrow[nt * 32 + lane];      // LDS.128: both ks fragments
                mma16816(d[0][nt], aF[0][0], wq.x, wq.y);
                mma16816(d[1][nt], aF[0][1], wq.x, wq.y);
                mma16816(d[0][nt], aF[1][0], wq.z, wq.w);
                mma16816(d[1][nt], aF[1][1], wq.z, wq.w);
            }
        }
        if (lane == 0) mbar_arrive(bbase + 24 + 8 * s);   // empty[s]: this warp done
        if (it >= 1 && it + 2 < 24) ISSUE(it + 2);
        if (++s == NSTAGE) s = 0;
    }
    #undef ISSUE
    __syncthreads();

    // ---- epilogue: fragments -> smem fp32 tile [128][129] ----
    float* sD = (float*)dsm;                       // 66048 B <= DSMEM
#pragma unroll
    for (int mt = 0; mt < 2; mt++) {
        int m0 = pxb + mt * 16 + (lane >> 2);
        int n0base = ntB * 8 + (lane & 3) * 2;
#pragma unroll
        for (int nt = 0; nt < 8; nt++) {
            int n0 = n0base + nt * 8;
            sD[m0 * 129 + n0]           = d[mt][nt][0];
            sD[m0 * 129 + n0 + 1]       = d[mt][nt][1];
            sD[(m0 + 8) * 129 + n0]     = d[mt][nt][2];
            sD[(m0 + 8) * 129 + n0 + 1] = d[mt][nt][3];
        }
    }
    __syncthreads();

    const float pav = pa[0];
#pragma unroll 1
    for (int k = 0; k < 2; k++) {
        int t = tid + k * NT;
        int px = t & 127, gl = t >> 7;               // gl 0..3
        int oc0 = ocH * 128 + gl * 32;
        if (MODE == 1) {
            uint32_t hv[16];
            unsigned short hprev = 0;
#pragma unroll
            for (int j = 0; j < 32; j++) {
                float v = sD[px * 129 + gl * 32 + j] + bias[oc0 + j];
                size_t xi = ((size_t)(b * Cn + oc0 + j) * Hn + y) * Wn + px;
                float m = fmaxf(aux[xi], v);
                xmOut[xi] = m;
                float tt = m >= 0.f ? m : pav * m;
                float a = fabsf(tt) >= 0.1f ? tt : 0.f;
                unsigned short hb = __half_as_ushort(__float2half_rn(a));
                if (j & 1) hv[j >> 1] = (uint32_t)hprev | ((uint32_t)hb << 16);
                else hprev = hb;
            }
            int gOut = ocH * 4 + gl;
            store_row64(actOut + ((size_t)(b * Hn + y) * 8 + gOut) * ABLK, px + 1, hv);
        } else {
#pragma unroll
            for (int j = 0; j < 32; j++) {
                float v = sD[px * 129 + gl * 32 + j] + bias[oc0 + j];
                out[((size_t)(b * Cn + oc0 + j) * Hn + y) * Wn + px] = v;
            }
        }
    }
}

// ---------------- host ----------------
extern "C" void kernel_launch(void* const* d_in, const int* in_sizes, int n_in,
                              void* d_out, int out_size) {
    const float* x  = (const float*)d_in[0];
    const float* w1 = (const float*)d_in[1];
    const float* b1 = (const float*)d_in[2];
    const float* w2 = (const float*)d_in[3];
    const float* b2 = (const float*)d_in[4];
    const float* w3 = (const float*)d_in[5];
    const float* b3 = (const float*)d_in[6];
    const float* pa = (const float*)d_in[7];
    float* out = (float*)d_out;

    unsigned char *wpk, *actA, *actB;
    float* xm;
    cudaGetSymbolAddress((void**)&wpk,  g_wpk);
    cudaGetSymbolAddress((void**)&xm,   g_xm);
    cudaGetSymbolAddress((void**)&actA, g_actA);
    cudaGetSymbolAddress((void**)&actB, g_actB);

    cudaFuncSetAttribute(conv_mma<1>, cudaFuncAttributeMaxDynamicSharedMemorySize, DSMEM);
    cudaFuncSetAttribute(conv_mma<3>, cudaFuncAttributeMaxDynamicSharedMemorySize, DSMEM);
    cudaFuncSetAttribute(k_prep, cudaFuncAttributeMaxDynamicSharedMemorySize, 131072);

    k_zero<<<(520 + 131072 + 255) / 256, 256>>>();
    k_packw<<<1152, 256>>>(w1, wpk);
    k_packw<<<1152, 256>>>(w2, wpk + WCONV);
    k_packw<<<1152, 256>>>(w3, wpk + 2 * WCONV);
    k_prep<<<dim3(Hn, Bn), 256, 131072>>>(x, pa);

    dim3 grid(2, Hn, Bn);
    // conv1: aux = x (xm needs no init)
    conv_mma<1><<<grid, NT, DSMEM>>>(actA, wpk,             b1, x,  xm, pa, actB, nullptr);
    conv_mma<1><<<grid, NT, DSMEM>>>(actB, wpk + WCONV,     b2, xm, xm, pa, actA, nullptr);
    conv_mma<3><<<grid, NT, DSMEM>>>(actA, wpk + 2 * WCONV, b3, nullptr, nullptr, pa, nullptr, out);
}

// round 14
// speedup vs baseline: 1.1795x; 1.0727x over previous
#include <cuda_runtime.h>
#include <cuda_fp16.h>
#include <cstdint>

#define Bn 8
#define Cn 256
#define Hn 128
#define Wn 128
#define NE (Bn*Cn*Hn*Wn)

// act block (b,y,g): 130 rows of 64B (fp16 x32ci), packed 2 rows per 128B line:
//   byte = L*128 + c*32 + par*16   (row = 2L+par, 16B piece c=0..3)
#define ABLK   8320                  // 65 lines * 128
#define ACT_TOT ((size_t)Bn*Hn*8*ABLK)
#define WSTG   24576                 // [kx3][nt16][lane32][uint4: ks0j0,ks0j1,ks1j0,ks1j1]
#define WCONV  (48ull*WSTG)
#define STG    (ABLK + WSTG)         // 32896
#define NSTAGE 3
#define DSMEM  (NSTAGE*STG)          // 98688  (>= 66048 epilogue tile)
#define NT 256                       // threads per conv CTA; 2 CTAs/SM

__device__ __align__(1024) unsigned char g_actA[ACT_TOT];
__device__ __align__(1024) unsigned char g_actB[ACT_TOT];
__device__ __align__(1024) unsigned char g_wpk[3*WCONV];
__device__ __align__(1024) unsigned char g_zero[ABLK];
__device__ float g_xm[NE];

// ---------------- helpers ----------------
static __device__ __forceinline__ uint32_t smem_u32(const void* p) {
    uint32_t r;
    asm("{ .reg .u64 t; cvta.to.shared.u64 t, %1; cvt.u32.u64 %0, t; }" : "=r"(r) : "l"(p));
    return r;
}
static __device__ __forceinline__ void cp16(uint32_t dst, const void* src) {
    asm volatile("cp.async.cg.shared.global [%0], [%1], 16;" :: "r"(dst), "l"(src) : "memory");
}
static __device__ __forceinline__ void mbar_init(uint32_t m, uint32_t cnt) {
    asm volatile("mbarrier.init.shared.b64 [%0], %1;" :: "r"(m), "r"(cnt) : "memory");
}
static __device__ __forceinline__ void cp_arrive(uint32_t m) {
    asm volatile("cp.async.mbarrier.arrive.noinc.shared::cta.b64 [%0];" :: "r"(m) : "memory");
}
static __device__ __forceinline__ void mbar_arrive(uint32_t m) {
    asm volatile("mbarrier.arrive.shared::cta.b64 _, [%0];" :: "r"(m) : "memory");
}
static __device__ __forceinline__ void mbar_wait(uint32_t m, uint32_t par) {
    uint32_t done = 0;
    while (!done) {
        asm volatile("{ .reg .pred p; mbarrier.try_wait.parity.acquire.cta.shared::cta.b64 p, [%1], %2, 0x989680; selp.b32 %0,1,0,p; }"
                     : "=r"(done) : "r"(m), "r"(par) : "memory");
    }
}
static __device__ __forceinline__ void ldm4(uint32_t a[4], uint32_t addr) {
    asm volatile("ldmatrix.sync.aligned.m8n8.x4.shared.b16 {%0,%1,%2,%3}, [%4];"
                 : "=r"(a[0]), "=r"(a[1]), "=r"(a[2]), "=r"(a[3]) : "r"(addr));
}
static __device__ __forceinline__ void mma16816(float d[4], const uint32_t a[4],
                                                uint32_t b0, uint32_t b1) {
    asm volatile("mma.sync.aligned.m16n8k16.row.col.f32.f16.f16.f32 "
                 "{%0,%1,%2,%3}, {%4,%5,%6,%7}, {%8,%9}, {%0,%1,%2,%3};"
                 : "+f"(d[0]), "+f"(d[1]), "+f"(d[2]), "+f"(d[3])
                 : "r"(a[0]), "r"(a[1]), "r"(a[2]), "r"(a[3]), "r"(b0), "r"(b1));
}
// store one 64B act row (row = 2L+par) into a block base (gmem, unswizzled)
static __device__ __forceinline__ void store_row64(unsigned char* blockbase, int row,
                                                   const uint32_t hv[16]) {
    unsigned char* base = blockbase + (row >> 1) * 128 + (row & 1) * 16;
#pragma unroll
    for (int c = 0; c < 4; c++)
        *(uint4*)(base + c * 32) = make_uint4(hv[4*c], hv[4*c+1], hv[4*c+2], hv[4*c+3]);
}

// ---------------- merged init: weight pack (x3 convs) + zero halos ----------------
// blocks [0, 3456): packw ; blocks [3456, 3456+1028): zero template + halo rows
__global__ void k_init(const float* __restrict__ w1, const float* __restrict__ w2,
                       const float* __restrict__ w3) {
    int blk = blockIdx.x;
    if (blk < 3456) {
        int cv = blk / 1152;
        const float* w = (cv == 0) ? w1 : (cv == 1) ? w2 : w3;
        unsigned char* dstB = g_wpk + (size_t)cv * WCONV;
        int u = (blk - cv * 1152) * 256 + threadIdx.x;
        if (u >= 294912) return;
        int within = u % 6144, stage = u / 6144;
        int g = stage & 7, kyH = stage >> 3;
        int ky = kyH % 3, ocH = kyH / 3;
        int kj = within & 3;  int ks = kj >> 1, j = kj & 1;
        int lane = (within >> 2) & 31;
        int nt   = (within >> 7) & 15;
        int kx   = within >> 11;
        int oc = ocH * 128 + nt * 8 + (lane >> 2);
        int k  = ks * 16 + (lane & 3) * 2 + j * 8;     // 0..31
        int ci0 = g * 32 + k;
        float e0 = w[((oc * Cn + ci0) * 3 + ky) * 3 + kx];
        float e1 = w[((oc * Cn + ci0 + 1) * 3 + ky) * 3 + kx];
        unsigned short h0 = __half_as_ushort(__float2half_rn(e0));
        unsigned short h1 = __half_as_ushort(__float2half_rn(e1));
        ((uint32_t*)dstB)[u] = (uint32_t)h0 | ((uint32_t)h1 << 16);
        return;
    }
    int i = (blk - 3456) * 256 + threadIdx.x;
    const uint4 z = make_uint4(0, 0, 0, 0);
    if (i < 520) { ((uint4*)g_zero)[i] = z; return; }
    int h = i - 520;
    if (h >= 2 * 8192 * 8) return;
    int j = h & 7;  h >>= 3;
    int blk2 = h & 8191;
    unsigned char* buf = (h >> 13) ? g_actB : g_actA;
    unsigned char* bb = buf + (size_t)blk2 * ABLK;
    if (j < 4) *(uint4*)(bb + j * 32) = z;                       // row 0
    else       *(uint4*)(bb + 64 * 128 + (j - 4) * 32 + 16) = z; // row 129
}

// ---------------- prep: act0 = fp16(mask(prelu(x))) ----------------
__global__ void k_prep(const float* __restrict__ x, const float* __restrict__ pa) {
    extern __shared__ float sX[];
    const int y = blockIdx.x, b = blockIdx.y, tid = threadIdx.x;
    const float pav = pa[0];
    const float4* src = (const float4*)(x + ((size_t)b * Cn * Hn + y) * Wn);
    for (int i = tid; i < 8192; i += 256) {
        int ci = i >> 5, p4 = i & 31;
        ((float4*)sX)[ci * 32 + p4] = src[(size_t)ci * (Hn * Wn / 4) + p4];
    }
    __syncthreads();
#pragma unroll 1
    for (int k = 0; k < 4; k++) {
        int t = tid + k * 256;
        int px = t & 127, g = t >> 7;
        uint32_t hv[16];
        unsigned short hprev = 0;
#pragma unroll
        for (int j = 0; j < 32; j++) {
            float v = sX[(g * 32 + j) * 128 + px];
            float tt = v >= 0.f ? v : pav * v;
            float a = fabsf(tt) >= 0.1f ? tt : 0.f;
            unsigned short hb = __half_as_ushort(__float2half_rn(a));
            if (j & 1) hv[j >> 1] = (uint32_t)hprev | ((uint32_t)hb << 16);
            else hprev = hb;
        }
        store_row64(g_actA + ((size_t)(b * Hn + y) * 8 + g) * ABLK, px + 1, hv);
    }
}

// ---------------- main conv: mma.sync implicit GEMM, unrolled mbarrier ring ----------------
// 256 thr: 4 M-warps (32 px) x 2 N-warps (64 oc); self-paced warps, 2 CTAs/SM
// MODE 1: y=conv+bias; m=max(aux,y); xmOut=m; actOut=pack(mask(prelu(m)))
// MODE 3: out(NCHW fp32) = conv+bias
template <int MODE>
__global__ __launch_bounds__(NT, 2)
void conv_mma(const unsigned char* __restrict__ actIn,
              const unsigned char* __restrict__ wcv,
              const float* __restrict__ bias,
              const float* __restrict__ aux,
              float* __restrict__ xmOut,
              const float* __restrict__ pa,
              unsigned char* __restrict__ actOut,
              float* __restrict__ out) {
    extern __shared__ __align__(16) unsigned char dsm[];
    __shared__ __align__(8) unsigned long long barsto[6];   // full[0..2], empty[0..2]
    const uint32_t sb = smem_u32(dsm);
    const uint32_t bbase = smem_u32(barsto);
    const int tid = threadIdx.x, lane = tid & 31, wid = tid >> 5;
    const int ocH = blockIdx.x, y = blockIdx.y, b = blockIdx.z;
    const int mw = wid & 3;                  // M-warp 0..3 (32 px each)
    const int pxb = mw * 32;
    const int ntB = (wid >> 2) * 8;          // N half

    if (tid == 0) {
        for (int s2 = 0; s2 < NSTAGE; s2++) {
            mbar_init(bbase + 8 * s2, NT);          // full: one cp-arrive per thread
            mbar_init(bbase + 24 + 8 * s2, 8);      // empty: one arrive per warp
        }
    }
    __syncthreads();

    float d[2][8][4];
#pragma unroll
    for (int mt = 0; mt < 2; mt++)
#pragma unroll
        for (int nt = 0; nt < 8; nt++)
#pragma unroll
            for (int q = 0; q < 4; q++) d[mt][nt][q] = 0.f;

    // issue this thread's cp slice for iteration IT (stage IT%3 -- constant-folded)
    #define ISSUE(IT) do { \
        int it_ = (IT); \
        int s_ = it_ % NSTAGE; \
        if (it_ >= NSTAGE) mbar_wait(bbase + 24 + 8 * s_, (it_ / NSTAGE - 1) & 1); \
        int ky_ = it_ >> 3, g_ = it_ & 7; \
        int ys_ = y + ky_ - 1; \
        const unsigned char* aSrc = ((unsigned)ys_ < (unsigned)Hn) \
            ? actIn + ((size_t)(b * Hn + ys_) * 8 + g_) * ABLK : g_zero; \
        const unsigned char* wSrc = wcv + (size_t)((ocH * 3 + ky_) * 8 + g_) * WSTG; \
        uint32_t ab = sb + s_ * STG; \
        for (int i = tid; i < 520; i += NT) { \
            int L = i >> 3, cc = (i >> 1) & 3, par = i & 1; \
            cp16(ab + L * 128 + ((cc ^ (L & 3)) << 5) + (par << 4), \
                 aSrc + L * 128 + cc * 32 + par * 16); \
        } \
        uint32_t wb = ab + ABLK; \
        for (int i = tid; i < 1536; i += NT) \
            cp16(wb + i * 16, wSrc + (size_t)i * 16); \
        cp_arrive(bbase + 8 * s_); \
    } while (0)

    // one pipeline step at compile-time stage S
    #define STEP(IT, S) do { \
        mbar_wait(bbase + 8 * (S), ((IT) / NSTAGE) & 1); \
        const uint32_t aB = sb + (S) * STG; \
        const unsigned char* wS = dsm + (S) * STG + ABLK; \
        _Pragma("unroll") \
        for (int kx = 0; kx < 3; kx++) { \
            uint32_t aF[2][2][4]; \
            _Pragma("unroll") \
            for (int mt = 0; mt < 2; mt++) { \
                int row = pxb + mt * 16 + (lane & 15) + kx; \
                int L = row >> 1, par = row & 1; \
                uint32_t base = aB + L * 128 + (par << 4); \
                _Pragma("unroll") \
                for (int ks = 0; ks < 2; ks++) { \
                    int c = ks * 2 + (lane >> 4); \
                    ldm4(aF[ks][mt], base + ((c ^ (L & 3)) << 5)); \
                } \
            } \
            const uint4* wrow = (const uint4*)(wS + ((size_t)(kx * 16 + ntB)) * 512); \
            _Pragma("unroll") \
            for (int nt = 0; nt < 8; nt++) { \
                uint4 wq = wrow[nt * 32 + lane]; \
                mma16816(d[0][nt], aF[0][0], wq.x, wq.y); \
                mma16816(d[1][nt], aF[0][1], wq.x, wq.y); \
                mma16816(d[0][nt], aF[1][0], wq.z, wq.w); \
                mma16816(d[1][nt], aF[1][1], wq.z, wq.w); \
            } \
        } \
        if (lane == 0) mbar_arrive(bbase + 24 + 8 * (S)); \
        if ((IT) >= 1 && (IT) + 2 < 24) ISSUE((IT) + 2); \
    } while (0)

    ISSUE(0); ISSUE(1); ISSUE(2);

#pragma unroll 1
    for (int m = 0; m < 8; m++) {
        const int it0 = 3 * m;
        STEP(it0 + 0, 0);
        STEP(it0 + 1, 1);
        STEP(it0 + 2, 2);
    }
    #undef STEP
    #undef ISSUE
    __syncthreads();

    // ---- epilogue: fragments -> smem fp32 tile [128][129] ----
    float* sD = (float*)dsm;                       // 66048 B <= DSMEM
#pragma unroll
    for (int mt = 0; mt < 2; mt++) {
        int m0 = pxb + mt * 16 + (lane >> 2);
        int n0base = ntB * 8 + (lane & 3) * 2;
#pragma unroll
        for (int nt = 0; nt < 8; nt++) {
            int n0 = n0base + nt * 8;
            sD[m0 * 129 + n0]           = d[mt][nt][0];
            sD[m0 * 129 + n0 + 1]       = d[mt][nt][1];
            sD[(m0 + 8) * 129 + n0]     = d[mt][nt][2];
            sD[(m0 + 8) * 129 + n0 + 1] = d[mt][nt][3];
        }
    }
    __syncthreads();

    const float pav = pa[0];
#pragma unroll 1
    for (int k = 0; k < 2; k++) {
        int t = tid + k * NT;
        int px = t & 127, gl = t >> 7;               // gl 0..3
        int oc0 = ocH * 128 + gl * 32;
        if (MODE == 1) {
            uint32_t hv[16];
            unsigned short hprev = 0;
#pragma unroll
            for (int j = 0; j < 32; j++) {
                float v = sD[px * 129 + gl * 32 + j] + bias[oc0 + j];
                size_t xi = ((size_t)(b * Cn + oc0 + j) * Hn + y) * Wn + px;
                float m = fmaxf(aux[xi], v);
                xmOut[xi] = m;
                float tt = m >= 0.f ? m : pav * m;
                float a = fabsf(tt) >= 0.1f ? tt : 0.f;
                unsigned short hb = __half_as_ushort(__float2half_rn(a));
                if (j & 1) hv[j >> 1] = (uint32_t)hprev | ((uint32_t)hb << 16);
                else hprev = hb;
            }
            int gOut = ocH * 4 + gl;
            store_row64(actOut + ((size_t)(b * Hn + y) * 8 + gOut) * ABLK, px + 1, hv);
        } else {
#pragma unroll
            for (int j = 0; j < 32; j++) {
                float v = sD[px * 129 + gl * 32 + j] + bias[oc0 + j];
                out[((size_t)(b * Cn + oc0 + j) * Hn + y) * Wn + px] = v;
            }
        }
    }
}

// ---------------- host ----------------
extern "C" void kernel_launch(void* const* d_in, const int* in_sizes, int n_in,
                              void* d_out, int out_size) {
    const float* x  = (const float*)d_in[0];
    const float* w1 = (const float*)d_in[1];
    const float* b1 = (const float*)d_in[2];
    const float* w2 = (const float*)d_in[3];
    const float* b2 = (const float*)d_in[4];
    const float* w3 = (const float*)d_in[5];
    const float* b3 = (const float*)d_in[6];
    const float* pa = (const float*)d_in[7];
    float* out = (float*)d_out;

    unsigned char *wpk, *actA, *actB;
    float* xm;
    cudaGetSymbolAddress((void**)&wpk,  g_wpk);
    cudaGetSymbolAddress((void**)&xm,   g_xm);
    cudaGetSymbolAddress((void**)&actA, g_actA);
    cudaGetSymbolAddress((void**)&actB, g_actB);

    cudaFuncSetAttribute(conv_mma<1>, cudaFuncAttributeMaxDynamicSharedMemorySize, DSMEM);
    cudaFuncSetAttribute(conv_mma<3>, cudaFuncAttributeMaxDynamicSharedMemorySize, DSMEM);
    cudaFuncSetAttribute(k_prep, cudaFuncAttributeMaxDynamicSharedMemorySize, 131072);

    k_init<<<3456 + 1028, 256>>>(w1, w2, w3);
    k_prep<<<dim3(Hn, Bn), 256, 131072>>>(x, pa);

    dim3 grid(2, Hn, Bn);
    // conv1: aux = x (xm needs no init)
    conv_mma<1><<<grid, NT, DSMEM>>>(actA, wpk,             b1, x,  xm, pa, actB, nullptr);
    conv_mma<1><<<grid, NT, DSMEM>>>(actB, wpk + WCONV,     b2, xm, xm, pa, actA, nullptr);
    conv_mma<3><<<grid, NT, DSMEM>>>(actA, wpk + 2 * WCONV, b3, nullptr, nullptr, pa, nullptr, out);
}

// round 15
// speedup vs baseline: 1.2043x; 1.0210x over previous
#include <cuda_runtime.h>
#include <cuda_fp16.h>
#include <cstdint>

#define Bn 8
#define Cn 256
#define Hn 128
#define Wn 128
#define NE (Bn*Cn*Hn*Wn)

// act block (b,y,g): 130 rows of 64B (fp16 x32ci), packed 2 rows per 128B line:
//   byte = L*128 + c*32 + par*16   (row = 2L+par, 16B piece c=0..3)
#define ABLK   8320                  // 65 lines * 128
#define ACT_TOT ((size_t)Bn*Hn*8*ABLK)
#define WSTG   24576                 // [kx3][nt16][lane32][uint4: ks0j0,ks0j1,ks1j0,ks1j1]
#define WCONV  (48ull*WSTG)
#define STG    (ABLK + WSTG)         // 32896
#define NSTAGE 3
#define DSMEM  (NSTAGE*STG)          // 98688  (>= 66048 epilogue tile)
#define NT 128                       // 4 warps: 2 M-warps x 2 N-warps; 2 CTAs/SM

__device__ __align__(1024) unsigned char g_actA[ACT_TOT];
__device__ __align__(1024) unsigned char g_actB[ACT_TOT];
__device__ __align__(1024) unsigned char g_wpk[3*WCONV];
__device__ __align__(1024) unsigned char g_zero[ABLK];
__device__ float g_xm[NE];

// ---------------- helpers ----------------
static __device__ __forceinline__ uint32_t smem_u32(const void* p) {
    uint32_t r;
    asm("{ .reg .u64 t; cvta.to.shared.u64 t, %1; cvt.u32.u64 %0, t; }" : "=r"(r) : "l"(p));
    return r;
}
static __device__ __forceinline__ void cp16(uint32_t dst, const void* src) {
    asm volatile("cp.async.cg.shared.global [%0], [%1], 16;" :: "r"(dst), "l"(src) : "memory");
}
static __device__ __forceinline__ void mbar_init(uint32_t m, uint32_t cnt) {
    asm volatile("mbarrier.init.shared.b64 [%0], %1;" :: "r"(m), "r"(cnt) : "memory");
}
static __device__ __forceinline__ void cp_arrive(uint32_t m) {
    asm volatile("cp.async.mbarrier.arrive.noinc.shared::cta.b64 [%0];" :: "r"(m) : "memory");
}
static __device__ __forceinline__ void mbar_arrive(uint32_t m) {
    asm volatile("mbarrier.arrive.shared::cta.b64 _, [%0];" :: "r"(m) : "memory");
}
static __device__ __forceinline__ void mbar_wait(uint32_t m, uint32_t par) {
    uint32_t done = 0;
    while (!done) {
        asm volatile("{ .reg .pred p; mbarrier.try_wait.parity.acquire.cta.shared::cta.b64 p, [%1], %2, 0x989680; selp.b32 %0,1,0,p; }"
                     : "=r"(done) : "r"(m), "r"(par) : "memory");
    }
}
static __device__ __forceinline__ void ldm4(uint32_t a[4], uint32_t addr) {
    asm volatile("ldmatrix.sync.aligned.m8n8.x4.shared.b16 {%0,%1,%2,%3}, [%4];"
                 : "=r"(a[0]), "=r"(a[1]), "=r"(a[2]), "=r"(a[3]) : "r"(addr));
}
static __device__ __forceinline__ void mma16816(float d[4], const uint32_t a[4],
                                                uint32_t b0, uint32_t b1) {
    asm volatile("mma.sync.aligned.m16n8k16.row.col.f32.f16.f16.f32 "
                 "{%0,%1,%2,%3}, {%4,%5,%6,%7}, {%8,%9}, {%0,%1,%2,%3};"
                 : "+f"(d[0]), "+f"(d[1]), "+f"(d[2]), "+f"(d[3])
                 : "r"(a[0]), "r"(a[1]), "r"(a[2]), "r"(a[3]), "r"(b0), "r"(b1));
}
// store one 64B act row (row = 2L+par) into a block base (gmem, unswizzled)
static __device__ __forceinline__ void store_row64(unsigned char* blockbase, int row,
                                                   const uint32_t hv[16]) {
    unsigned char* base = blockbase + (row >> 1) * 128 + (row & 1) * 16;
#pragma unroll
    for (int c = 0; c < 4; c++)
        *(uint4*)(base + c * 32) = make_uint4(hv[4*c], hv[4*c+1], hv[4*c+2], hv[4*c+3]);
}

// ---------------- merged init: weight pack (x3 convs) + zero halos ----------------
__global__ void k_init(const float* __restrict__ w1, const float* __restrict__ w2,
                       const float* __restrict__ w3) {
    int blk = blockIdx.x;
    if (blk < 3456) {
        int cv = blk / 1152;
        const float* w = (cv == 0) ? w1 : (cv == 1) ? w2 : w3;
        unsigned char* dstB = g_wpk + (size_t)cv * WCONV;
        int u = (blk - cv * 1152) * 256 + threadIdx.x;
        if (u >= 294912) return;
        int within = u % 6144, stage = u / 6144;
        int g = stage & 7, kyH = stage >> 3;
        int ky = kyH % 3, ocH = kyH / 3;
        int kj = within & 3;  int ks = kj >> 1, j = kj & 1;
        int lane = (within >> 2) & 31;
        int nt   = (within >> 7) & 15;
        int kx   = within >> 11;
        int oc = ocH * 128 + nt * 8 + (lane >> 2);
        int k  = ks * 16 + (lane & 3) * 2 + j * 8;     // 0..31
        int ci0 = g * 32 + k;
        float e0 = w[((oc * Cn + ci0) * 3 + ky) * 3 + kx];
        float e1 = w[((oc * Cn + ci0 + 1) * 3 + ky) * 3 + kx];
        unsigned short h0 = __half_as_ushort(__float2half_rn(e0));
        unsigned short h1 = __half_as_ushort(__float2half_rn(e1));
        ((uint32_t*)dstB)[u] = (uint32_t)h0 | ((uint32_t)h1 << 16);
        return;
    }
    int i = (blk - 3456) * 256 + threadIdx.x;
    const uint4 z = make_uint4(0, 0, 0, 0);
    if (i < 520) { ((uint4*)g_zero)[i] = z; return; }
    int h = i - 520;
    if (h >= 2 * 8192 * 8) return;
    int j = h & 7;  h >>= 3;
    int blk2 = h & 8191;
    unsigned char* buf = (h >> 13) ? g_actB : g_actA;
    unsigned char* bb = buf + (size_t)blk2 * ABLK;
    if (j < 4) *(uint4*)(bb + j * 32) = z;                       // row 0
    else       *(uint4*)(bb + 64 * 128 + (j - 4) * 32 + 16) = z; // row 129
}

// ---------------- prep: act0 = fp16(mask(prelu(x))) ----------------
__global__ void k_prep(const float* __restrict__ x, const float* __restrict__ pa) {
    extern __shared__ float sX[];
    const int y = blockIdx.x, b = blockIdx.y, tid = threadIdx.x;
    const float pav = pa[0];
    const float4* src = (const float4*)(x + ((size_t)b * Cn * Hn + y) * Wn);
    for (int i = tid; i < 8192; i += 256) {
        int ci = i >> 5, p4 = i & 31;
        ((float4*)sX)[ci * 32 + p4] = src[(size_t)ci * (Hn * Wn / 4) + p4];
    }
    __syncthreads();
#pragma unroll 1
    for (int k = 0; k < 4; k++) {
        int t = tid + k * 256;
        int px = t & 127, g = t >> 7;
        uint32_t hv[16];
        unsigned short hprev = 0;
#pragma unroll
        for (int j = 0; j < 32; j++) {
            float v = sX[(g * 32 + j) * 128 + px];
            float tt = v >= 0.f ? v : pav * v;
            float a = fabsf(tt) >= 0.1f ? tt : 0.f;
            unsigned short hb = __half_as_ushort(__float2half_rn(a));
            if (j & 1) hv[j >> 1] = (uint32_t)hprev | ((uint32_t)hb << 16);
            else hprev = hb;
        }
        store_row64(g_actA + ((size_t)(b * Hn + y) * 8 + g) * ABLK, px + 1, hv);
    }
}

// ---------------- main conv: 64x64 warp tile, mbarrier ring, 2 CTAs/SM ----------------
// 128 thr: 2 M-warps (64 px) x 2 N-warps (64 oc)
// MODE 1: y=conv+bias; m=max(aux,y); xmOut=m; actOut=pack(mask(prelu(m)))
// MODE 3: out(NCHW fp32) = conv+bias
template <int MODE>
__global__ __launch_bounds__(NT, 2)
void conv_mma(const unsigned char* __restrict__ actIn,
              const unsigned char* __restrict__ wcv,
              const float* __restrict__ bias,
              const float* __restrict__ aux,
              float* __restrict__ xmOut,
              const float* __restrict__ pa,
              unsigned char* __restrict__ actOut,
              float* __restrict__ out) {
    extern __shared__ __align__(16) unsigned char dsm[];
    __shared__ __align__(8) unsigned long long barsto[6];   // full[0..2], empty[0..2]
    const uint32_t sb = smem_u32(dsm);
    const uint32_t bbase = smem_u32(barsto);
    const int tid = threadIdx.x, lane = tid & 31, wid = tid >> 5;
    const int ocH = blockIdx.x, y = blockIdx.y, b = blockIdx.z;
    const int mw = wid & 1;                  // M-warp 0..1 (64 px each)
    const int pxb = mw * 64;
    const int ntB = (wid >> 1) * 8;          // N half: 8 n8-tiles

    if (tid == 0) {
        for (int s2 = 0; s2 < NSTAGE; s2++) {
            mbar_init(bbase + 8 * s2, NT);          // full: one cp-arrive per thread
            mbar_init(bbase + 24 + 8 * s2, 4);      // empty: one arrive per warp
        }
    }
    __syncthreads();

    float d[4][8][4];                        // [mt 4][nt 8][quad] = 128 accum regs
#pragma unroll
    for (int mt = 0; mt < 4; mt++)
#pragma unroll
        for (int nt = 0; nt < 8; nt++)
#pragma unroll
            for (int q = 0; q < 4; q++) d[mt][nt][q] = 0.f;

    // issue this thread's cp slice for iteration IT (stage IT%3 -- constant-folded)
    #define ISSUE(IT) do { \
        int it_ = (IT); \
        int s_ = it_ % NSTAGE; \
        if (it_ >= NSTAGE) mbar_wait(bbase + 24 + 8 * s_, (it_ / NSTAGE - 1) & 1); \
        int ky_ = it_ >> 3, g_ = it_ & 7; \
        int ys_ = y + ky_ - 1; \
        const unsigned char* aSrc = ((unsigned)ys_ < (unsigned)Hn) \
            ? actIn + ((size_t)(b * Hn + ys_) * 8 + g_) * ABLK : g_zero; \
        const unsigned char* wSrc = wcv + (size_t)((ocH * 3 + ky_) * 8 + g_) * WSTG; \
        uint32_t ab = sb + s_ * STG; \
        for (int i = tid; i < 520; i += NT) { \
            int L = i >> 3, cc = (i >> 1) & 3, par = i & 1; \
            cp16(ab + L * 128 + ((cc ^ (L & 3)) << 5) + (par << 4), \
                 aSrc + L * 128 + cc * 32 + par * 16); \
        } \
        uint32_t wb = ab + ABLK; \
        for (int i = tid; i < 1536; i += NT) \
            cp16(wb + i * 16, wSrc + (size_t)i * 16); \
        cp_arrive(bbase + 8 * s_); \
    } while (0)

    // one pipeline step at compile-time stage S
    #define STEP(IT, S) do { \
        mbar_wait(bbase + 8 * (S), ((IT) / NSTAGE) & 1); \
        const uint32_t aB = sb + (S) * STG; \
        const unsigned char* wS = dsm + (S) * STG + ABLK; \
        _Pragma("unroll") \
        for (int kx = 0; kx < 3; kx++) { \
            uint32_t aF[2][4][4]; \
            _Pragma("unroll") \
            for (int mt = 0; mt < 4; mt++) { \
                int row = pxb + mt * 16 + (lane & 15) + kx; \
                int L = row >> 1, par = row & 1; \
                uint32_t base = aB + L * 128 + (par << 4); \
                _Pragma("unroll") \
                for (int ks = 0; ks < 2; ks++) { \
                    int c = ks * 2 + (lane >> 4); \
                    ldm4(aF[ks][mt], base + ((c ^ (L & 3)) << 5)); \
                } \
            } \
            const uint4* wrow = (const uint4*)(wS + ((size_t)(kx * 16 + ntB)) * 512); \
            _Pragma("unroll") \
            for (int nt = 0; nt < 8; nt++) { \
                uint4 wq = wrow[nt * 32 + lane]; \
                _Pragma("unroll") \
                for (int mt = 0; mt < 4; mt++) { \
                    mma16816(d[mt][nt], aF[0][mt], wq.x, wq.y); \
                    mma16816(d[mt][nt], aF[1][mt], wq.z, wq.w); \
                } \
            } \
        } \
        if (lane == 0) mbar_arrive(bbase + 24 + 8 * (S)); \
        if ((IT) >= 1 && (IT) + 2 < 24) ISSUE((IT) + 2); \
    } while (0)

    ISSUE(0); ISSUE(1); ISSUE(2);

#pragma unroll 1
    for (int m = 0; m < 8; m++) {
        const int it0 = 3 * m;
        STEP(it0 + 0, 0);
        STEP(it0 + 1, 1);
        STEP(it0 + 2, 2);
    }
    #undef STEP
    #undef ISSUE
    __syncthreads();

    // ---- epilogue: fragments -> smem fp32 tile [128][129] ----
    float* sD = (float*)dsm;                       // 66048 B <= DSMEM
#pragma unroll
    for (int mt = 0; mt < 4; mt++) {
        int m0 = pxb + mt * 16 + (lane >> 2);
        int n0base = ntB * 8 + (lane & 3) * 2;
#pragma unroll
        for (int nt = 0; nt < 8; nt++) {
            int n0 = n0base + nt * 8;
            sD[m0 * 129 + n0]           = d[mt][nt][0];
            sD[m0 * 129 + n0 + 1]       = d[mt][nt][1];
            sD[(m0 + 8) * 129 + n0]     = d[mt][nt][2];
            sD[(m0 + 8) * 129 + n0 + 1] = d[mt][nt][3];
        }
    }
    __syncthreads();

    const float pav = pa[0];
#pragma unroll 1
    for (int k = 0; k < 4; k++) {
        int t = tid + k * NT;
        int px = t & 127, gl = t >> 7;               // gl 0..3
        int oc0 = ocH * 128 + gl * 32;
        if (MODE == 1) {
            uint32_t hv[16];
            unsigned short hprev = 0;
#pragma unroll
            for (int j = 0; j < 32; j++) {
                float v = sD[px * 129 + gl * 32 + j] + bias[oc0 + j];
                size_t xi = ((size_t)(b * Cn + oc0 + j) * Hn + y) * Wn + px;
                float m = fmaxf(aux[xi], v);
                xmOut[xi] = m;
                float tt = m >= 0.f ? m : pav * m;
                float a = fabsf(tt) >= 0.1f ? tt : 0.f;
                unsigned short hb = __half_as_ushort(__float2half_rn(a));
                if (j & 1) hv[j >> 1] = (uint32_t)hprev | ((uint32_t)hb << 16);
                else hprev = hb;
            }
            int gOut = ocH * 4 + gl;
            store_row64(actOut + ((size_t)(b * Hn + y) * 8 + gOut) * ABLK, px + 1, hv);
        } else {
#pragma unroll
            for (int j = 0; j < 32; j++) {
                float v = sD[px * 129 + gl * 32 + j] + bias[oc0 + j];
                out[((size_t)(b * Cn + oc0 + j) * Hn + y) * Wn + px] = v;
            }
        }
    }
}

// ---------------- host ----------------
extern "C" void kernel_launch(void* const* d_in, const int* in_sizes, int n_in,
                              void* d_out, int out_size) {
    const float* x  = (const float*)d_in[0];
    const float* w1 = (const float*)d_in[1];
    const float* b1 = (const float*)d_in[2];
    const float* w2 = (const float*)d_in[3];
    const float* b2 = (const float*)d_in[4];
    const float* w3 = (const float*)d_in[5];
    const float* b3 = (const float*)d_in[6];
    const float* pa = (const float*)d_in[7];
    float* out = (float*)d_out;

    unsigned char *wpk, *actA, *actB;
    float* xm;
    cudaGetSymbolAddress((void**)&wpk,  g_wpk);
    cudaGetSymbolAddress((void**)&xm,   g_xm);
    cudaGetSymbolAddress((void**)&actA, g_actA);
    cudaGetSymbolAddress((void**)&actB, g_actB);

    cudaFuncSetAttribute(conv_mma<1>, cudaFuncAttributeMaxDynamicSharedMemorySize, DSMEM);
    cudaFuncSetAttribute(conv_mma<3>, cudaFuncAttributeMaxDynamicSharedMemorySize, DSMEM);
    cudaFuncSetAttribute(k_prep, cudaFuncAttributeMaxDynamicSharedMemorySize, 131072);

    k_init<<<3456 + 1028, 256>>>(w1, w2, w3);
    k_prep<<<dim3(Hn, Bn), 256, 131072>>>(x, pa);

    dim3 grid(2, Hn, Bn);
    // conv1: aux = x (xm needs no init)
    conv_mma<1><<<grid, NT, DSMEM>>>(actA, wpk,             b1, x,  xm, pa, actB, nullptr);
    conv_mma<1><<<grid, NT, DSMEM>>>(actB, wpk + WCONV,     b2, xm, xm, pa, actA, nullptr);
    conv_mma<3><<<grid, NT, DSMEM>>>(actA, wpk + 2 * WCONV, b3, nullptr, nullptr, pa, nullptr, out);
}

// round 16
// speedup vs baseline: 1.3671x; 1.1352x over previous
#include <cuda_runtime.h>
#include <cuda_fp16.h>
#include <cstdint>

#define Bn 8
#define Cn 256
#define Hn 128
#define Wn 128
#define NE (Bn*Cn*Hn*Wn)

// act block (b,y,g): 130 rows of 64B (fp16 x32ci), 2 rows per 128B line, SWIZZLED IN GMEM:
//   byte = L*128 + ((c ^ (L&3))<<5) + par*16   (row = 2L+par, 16B piece c=0..3)
#define ABLK   8320                  // 65 lines * 128
#define ACT_TOT ((size_t)Bn*Hn*8*ABLK)
#define WSTG   24576                 // [kx3][nt16][lane32][uint4: ks0j0,ks0j1,ks1j0,ks1j1]
#define WCONV  (48ull*WSTG)
#define STG    (ABLK + WSTG)         // 32896
#define NSTAGE 3
#define DSMEM  (NSTAGE*STG)          // 98688  (>= 66048 epilogue tile)
#define NT 128                       // 4 warps: 2 M-warps x 2 N-warps; 2 CTAs/SM

__device__ __align__(1024) unsigned char g_actA[ACT_TOT];
__device__ __align__(1024) unsigned char g_actB[ACT_TOT];
__device__ __align__(1024) unsigned char g_wpk[3*WCONV];
__device__ __align__(1024) unsigned char g_zero[ABLK];
__device__ float g_xm[NE];

// ---------------- helpers ----------------
static __device__ __forceinline__ uint32_t smem_u32(const void* p) {
    uint32_t r;
    asm("{ .reg .u64 t; cvta.to.shared.u64 t, %1; cvt.u32.u64 %0, t; }" : "=r"(r) : "l"(p));
    return r;
}
static __device__ __forceinline__ void mbar_init(uint32_t m, uint32_t cnt) {
    asm volatile("mbarrier.init.shared.b64 [%0], %1;" :: "r"(m), "r"(cnt) : "memory");
}
static __device__ __forceinline__ void mbar_expect(uint32_t m, uint32_t tx) {
    asm volatile("mbarrier.arrive.expect_tx.shared.b64 _, [%0], %1;" :: "r"(m), "r"(tx) : "memory");
}
static __device__ __forceinline__ void bulk_cp(uint32_t dst, const void* src, uint32_t sz, uint32_t mbar) {
    asm volatile("cp.async.bulk.shared::cta.global.mbarrier::complete_tx::bytes [%0], [%1], %2, [%3];"
                 :: "r"(dst), "l"(src), "r"(sz), "r"(mbar) : "memory");
}
static __device__ __forceinline__ void mbar_arrive(uint32_t m) {
    asm volatile("mbarrier.arrive.shared::cta.b64 _, [%0];" :: "r"(m) : "memory");
}
static __device__ __forceinline__ void mbar_wait(uint32_t m, uint32_t par) {
    uint32_t done = 0;
    while (!done) {
        asm volatile("{ .reg .pred p; mbarrier.try_wait.parity.acquire.cta.shared::cta.b64 p, [%1], %2, 0x989680; selp.b32 %0,1,0,p; }"
                     : "=r"(done) : "r"(m), "r"(par) : "memory");
    }
}
static __device__ __forceinline__ void ldm4(uint32_t a[4], uint32_t addr) {
    asm volatile("ldmatrix.sync.aligned.m8n8.x4.shared.b16 {%0,%1,%2,%3}, [%4];"
                 : "=r"(a[0]), "=r"(a[1]), "=r"(a[2]), "=r"(a[3]) : "r"(addr));
}
static __device__ __forceinline__ void mma16816(float d[4], const uint32_t a[4],
                                                uint32_t b0, uint32_t b1) {
    asm volatile("mma.sync.aligned.m16n8k16.row.col.f32.f16.f16.f32 "
                 "{%0,%1,%2,%3}, {%4,%5,%6,%7}, {%8,%9}, {%0,%1,%2,%3};"
                 : "+f"(d[0]), "+f"(d[1]), "+f"(d[2]), "+f"(d[3])
                 : "r"(a[0]), "r"(a[1]), "r"(a[2]), "r"(a[3]), "r"(b0), "r"(b1));
}
// store one 64B act row (row = 2L+par), gmem-SWIZZLED layout
static __device__ __forceinline__ void store_row64(unsigned char* blockbase, int row,
                                                   const uint32_t hv[16]) {
    int L = row >> 1, par = row & 1;
    unsigned char* base = blockbase + L * 128 + par * 16;
#pragma unroll
    for (int c = 0; c < 4; c++)
        *(uint4*)(base + ((c ^ (L & 3)) << 5)) = make_uint4(hv[4*c], hv[4*c+1], hv[4*c+2], hv[4*c+3]);
}

// ---------------- merged init: weight pack (x3 convs) + zero halos ----------------
__global__ void k_init(const float* __restrict__ w1, const float* __restrict__ w2,
                       const float* __restrict__ w3) {
    int blk = blockIdx.x;
    if (blk < 3456) {
        int cv = blk / 1152;
        const float* w = (cv == 0) ? w1 : (cv == 1) ? w2 : w3;
        unsigned char* dstB = g_wpk + (size_t)cv * WCONV;
        int u = (blk - cv * 1152) * 256 + threadIdx.x;
        if (u >= 294912) return;
        int within = u % 6144, stage = u / 6144;
        int g = stage & 7, kyH = stage >> 3;
        int ky = kyH % 3, ocH = kyH / 3;
        int kj = within & 3;  int ks = kj >> 1, j = kj & 1;
        int lane = (within >> 2) & 31;
        int nt   = (within >> 7) & 15;
        int kx   = within >> 11;
        int oc = ocH * 128 + nt * 8 + (lane >> 2);
        int k  = ks * 16 + (lane & 3) * 2 + j * 8;     // 0..31
        int ci0 = g * 32 + k;
        float e0 = w[((oc * Cn + ci0) * 3 + ky) * 3 + kx];
        float e1 = w[((oc * Cn + ci0 + 1) * 3 + ky) * 3 + kx];
        unsigned short h0 = __half_as_ushort(__float2half_rn(e0));
        unsigned short h1 = __half_as_ushort(__float2half_rn(e1));
        ((uint32_t*)dstB)[u] = (uint32_t)h0 | ((uint32_t)h1 << 16);
        return;
    }
    int i = (blk - 3456) * 256 + threadIdx.x;
    const uint4 z = make_uint4(0, 0, 0, 0);
    if (i < 520) { ((uint4*)g_zero)[i] = z; return; }
    int h = i - 520;
    if (h >= 2 * 8192 * 8) return;
    int j = h & 7;  h >>= 3;
    int blk2 = h & 8191;
    unsigned char* buf = (h >> 13) ? g_actB : g_actA;
    unsigned char* bb = buf + (size_t)blk2 * ABLK;
    // rows 0 (L=0) and 129 (L=64): L&3==0 -> swizzle identity, plain writes
    if (j < 4) *(uint4*)(bb + j * 32) = z;                       // row 0
    else       *(uint4*)(bb + 64 * 128 + (j - 4) * 32 + 16) = z; // row 129
}

// ---------------- prep: act0 = fp16(mask(prelu(x))) ----------------
__global__ void k_prep(const float* __restrict__ x, const float* __restrict__ pa) {
    extern __shared__ float sX[];
    const int y = blockIdx.x, b = blockIdx.y, tid = threadIdx.x;
    const float pav = pa[0];
    const float4* src = (const float4*)(x + ((size_t)b * Cn * Hn + y) * Wn);
    for (int i = tid; i < 8192; i += 256) {
        int ci = i >> 5, p4 = i & 31;
        ((float4*)sX)[ci * 32 + p4] = src[(size_t)ci * (Hn * Wn / 4) + p4];
    }
    __syncthreads();
#pragma unroll 1
    for (int k = 0; k < 4; k++) {
        int t = tid + k * 256;
        int px = t & 127, g = t >> 7;
        uint32_t hv[16];
        unsigned short hprev = 0;
#pragma unroll
        for (int j = 0; j < 32; j++) {
            float v = sX[(g * 32 + j) * 128 + px];
            float tt = v >= 0.f ? v : pav * v;
            float a = fabsf(tt) >= 0.1f ? tt : 0.f;
            unsigned short hb = __half_as_ushort(__float2half_rn(a));
            if (j & 1) hv[j >> 1] = (uint32_t)hprev | ((uint32_t)hb << 16);
            else hprev = hb;
        }
        store_row64(g_actA + ((size_t)(b * Hn + y) * 8 + g) * ABLK, px + 1, hv);
    }
}

// ---------------- main conv: 64x64 warp tile, bulk-copy mbarrier ring, 2 CTAs/SM ----------------
// 128 thr: 2 M-warps (64 px) x 2 N-warps (64 oc); tid 0 = sole producer (2 bulk cps/stage)
// MODE 1: y=conv+bias; m=max(aux,y); xmOut=m; actOut=pack(mask(prelu(m)))
// MODE 3: out(NCHW fp32) = conv+bias
template <int MODE>
__global__ __launch_bounds__(NT, 2)
void conv_mma(const unsigned char* __restrict__ actIn,
              const unsigned char* __restrict__ wcv,
              const float* __restrict__ bias,
              const float* __restrict__ aux,
              float* __restrict__ xmOut,
              const float* __restrict__ pa,
              unsigned char* __restrict__ actOut,
              float* __restrict__ out) {
    extern __shared__ __align__(16) unsigned char dsm[];
    __shared__ __align__(8) unsigned long long barsto[6];   // full[0..2], empty[0..2]
    const uint32_t sb = smem_u32(dsm);
    const uint32_t bbase = smem_u32(barsto);
    const int tid = threadIdx.x, lane = tid & 31, wid = tid >> 5;
    const int ocH = blockIdx.x, y = blockIdx.y, b = blockIdx.z;
    const int mw = wid & 1;                  // M-warp 0..1 (64 px each)
    const int pxb = mw * 64;
    const int ntB = (wid >> 1) * 8;          // N half: 8 n8-tiles

    if (tid == 0) {
        for (int s2 = 0; s2 < NSTAGE; s2++) {
            mbar_init(bbase + 8 * s2, 1);           // full: producer expect_tx arrive
            mbar_init(bbase + 24 + 8 * s2, 4);      // empty: one arrive per warp
        }
    }
    __syncthreads();

    float d[4][8][4];                        // [mt 4][nt 8][quad] = 128 accum regs
#pragma unroll
    for (int mt = 0; mt < 4; mt++)
#pragma unroll
        for (int nt = 0; nt < 8; nt++)
#pragma unroll
            for (int q = 0; q < 4; q++) d[mt][nt][q] = 0.f;

    // producer: stage IT%3, tid 0 only -- 2 bulk copies + expect_tx
    #define ISSUE(IT) do { \
        if (tid == 0) { \
            int it_ = (IT); \
            int s_ = it_ % NSTAGE; \
            if (it_ >= NSTAGE) mbar_wait(bbase + 24 + 8 * s_, (it_ / NSTAGE - 1) & 1); \
            int ky_ = it_ >> 3, g_ = it_ & 7; \
            int ys_ = y + ky_ - 1; \
            const unsigned char* aSrc = ((unsigned)ys_ < (unsigned)Hn) \
                ? actIn + ((size_t)(b * Hn + ys_) * 8 + g_) * ABLK : g_zero; \
            const unsigned char* wSrc = wcv + (size_t)((ocH * 3 + ky_) * 8 + g_) * WSTG; \
            uint32_t ab = sb + s_ * STG; \
            uint32_t fm = bbase + 8 * s_; \
            mbar_expect(fm, STG); \
            bulk_cp(ab, aSrc, ABLK, fm); \
            bulk_cp(ab + ABLK, wSrc, WSTG, fm); \
        } \
    } while (0)

    // one pipeline step at compile-time stage S
    #define STEP(IT, S) do { \
        mbar_wait(bbase + 8 * (S), ((IT) / NSTAGE) & 1); \
        const uint32_t aB = sb + (S) * STG; \
        const unsigned char* wS = dsm + (S) * STG + ABLK; \
        _Pragma("unroll") \
        for (int kx = 0; kx < 3; kx++) { \
            uint32_t aF[2][4][4]; \
            _Pragma("unroll") \
            for (int mt = 0; mt < 4; mt++) { \
                int row = pxb + mt * 16 + (lane & 15) + kx; \
                int L = row >> 1, par = row & 1; \
                uint32_t base = aB + L * 128 + (par << 4); \
                _Pragma("unroll") \
                for (int ks = 0; ks < 2; ks++) { \
                    int c = ks * 2 + (lane >> 4); \
                    ldm4(aF[ks][mt], base + ((c ^ (L & 3)) << 5)); \
                } \
            } \
            const uint4* wrow = (const uint4*)(wS + ((size_t)(kx * 16 + ntB)) * 512); \
            _Pragma("unroll") \
            for (int nt = 0; nt < 8; nt++) { \
                uint4 wq = wrow[nt * 32 + lane]; \
                _Pragma("unroll") \
                for (int mt = 0; mt < 4; mt++) { \
                    mma16816(d[mt][nt], aF[0][mt], wq.x, wq.y); \
                    mma16816(d[mt][nt], aF[1][mt], wq.z, wq.w); \
                } \
            } \
        } \
        if (lane == 0) mbar_arrive(bbase + 24 + 8 * (S)); \
        if ((IT) >= 1 && (IT) + 2 < 24) ISSUE((IT) + 2); \
    } while (0)

    ISSUE(0); ISSUE(1); ISSUE(2);

#pragma unroll 1
    for (int m = 0; m < 8; m++) {
        const int it0 = 3 * m;
        STEP(it0 + 0, 0);
        STEP(it0 + 1, 1);
        STEP(it0 + 2, 2);
    }
    #undef STEP
    #undef ISSUE
    __syncthreads();

    // ---- epilogue: fragments -> smem fp32 tile [128][129] ----
    float* sD = (float*)dsm;                       // 66048 B <= DSMEM
#pragma unroll
    for (int mt = 0; mt < 4; mt++) {
        int m0 = pxb + mt * 16 + (lane >> 2);
        int n0base = ntB * 8 + (lane & 3) * 2;
#pragma unroll
        for (int nt = 0; nt < 8; nt++) {
            int n0 = n0base + nt * 8;
            sD[m0 * 129 + n0]           = d[mt][nt][0];
            sD[m0 * 129 + n0 + 1]       = d[mt][nt][1];
            sD[(m0 + 8) * 129 + n0]     = d[mt][nt][2];
            sD[(m0 + 8) * 129 + n0 + 1] = d[mt][nt][3];
        }
    }
    __syncthreads();

    const float pav = pa[0];
#pragma unroll 1
    for (int k = 0; k < 4; k++) {
        int t = tid + k * NT;
        int px = t & 127, gl = t >> 7;               // gl 0..3
        int oc0 = ocH * 128 + gl * 32;
        if (MODE == 1) {
            uint32_t hv[16];
            unsigned short hprev = 0;
#pragma unroll
            for (int j = 0; j < 32; j++) {
                float v = sD[px * 129 + gl * 32 + j] + bias[oc0 + j];
                size_t xi = ((size_t)(b * Cn + oc0 + j) * Hn + y) * Wn + px;
                float m = fmaxf(aux[xi], v);
                xmOut[xi] = m;
                float tt = m >= 0.f ? m : pav * m;
                float a = fabsf(tt) >= 0.1f ? tt : 0.f;
                unsigned short hb = __half_as_ushort(__float2half_rn(a));
                if (j & 1) hv[j >> 1] = (uint32_t)hprev | ((uint32_t)hb << 16);
                else hprev = hb;
            }
            int gOut = ocH * 4 + gl;
            store_row64(actOut + ((size_t)(b * Hn + y) * 8 + gOut) * ABLK, px + 1, hv);
        } else {
#pragma unroll
            for (int j = 0; j < 32; j++) {
                float v = sD[px * 129 + gl * 32 + j] + bias[oc0 + j];
                out[((size_t)(b * Cn + oc0 + j) * Hn + y) * Wn + px] = v;
            }
        }
    }
}

// ---------------- host ----------------
extern "C" void kernel_launch(void* const* d_in, const int* in_sizes, int n_in,
                              void* d_out, int out_size) {
    const float* x  = (const float*)d_in[0];
    const float* w1 = (const float*)d_in[1];
    const float* b1 = (const float*)d_in[2];
    const float* w2 = (const float*)d_in[3];
    const float* b2 = (const float*)d_in[4];
    const float* w3 = (const float*)d_in[5];
    const float* b3 = (const float*)d_in[6];
    const float* pa = (const float*)d_in[7];
    float* out = (float*)d_out;

    unsigned char *wpk, *actA, *actB;
    float* xm;
    cudaGetSymbolAddress((void**)&wpk,  g_wpk);
    cudaGetSymbolAddress((void**)&xm,   g_xm);
    cudaGetSymbolAddress((void**)&actA, g_actA);
    cudaGetSymbolAddress((void**)&actB, g_actB);

    cudaFuncSetAttribute(conv_mma<1>, cudaFuncAttributeMaxDynamicSharedMemorySize, DSMEM);
    cudaFuncSetAttribute(conv_mma<3>, cudaFuncAttributeMaxDynamicSharedMemorySize, DSMEM);
    cudaFuncSetAttribute(k_prep, cudaFuncAttributeMaxDynamicSharedMemorySize, 131072);

    k_init<<<3456 + 1028, 256>>>(w1, w2, w3);
    k_prep<<<dim3(Hn, Bn), 256, 131072>>>(x, pa);

    dim3 grid(2, Hn, Bn);
    // conv1: aux = x (xm needs no init)
    conv_mma<1><<<grid, NT, DSMEM>>>(actA, wpk,             b1, x,  xm, pa, actB, nullptr);
    conv_mma<1><<<grid, NT, DSMEM>>>(actB, wpk + WCONV,     b2, xm, xm, pa, actA, nullptr);
    conv_mma<3><<<grid, NT, DSMEM>>>(actA, wpk + 2 * WCONV, b3, nullptr, nullptr, pa, nullptr, out);
}